// round 1
// baseline (speedup 1.0000x reference)
#include <cuda_runtime.h>
#include <cstdint>

// ---------------------------------------------------------------------------
// ComplementaryAttention  B=4 T=1024 D=512 H=8 hd=64
//
// Pipeline (all fp32, round-1 baseline):
//   1.  q,k,v   = x @ W + b                    (3x gemm_bias)
//   2.  A_t     = softmax(q k^T * hd^-0.5)     (scores gemm + row softmax)
//   3.  z       = sum_h A_t[h]*cw[h] + cb      (mask logit; M_f = z<=0, M_r = z>=0)
//   4.  row stats (max, 1/sumexp) for softmax(A_t*M_f) and softmax(A_t*M_r)
//   5.  T_f = A_f @ v, T_r = A_r @ v   with A_f/A_r regenerated on the fly
//   6.  F_f,G_f,F_r,G_r = T @ W + b            (4x gemm_bias)
//   7.  out = F_f*sig(sig(G_f)-sig(G_r)) + F_r*(1-...)
// ---------------------------------------------------------------------------

#define NT 256

// scratch layout (floats)
#define OFF_Q   (0ull)
#define OFF_K   (2ull  * 1024 * 1024)
#define OFF_V   (4ull  * 1024 * 1024)
#define OFF_TF  (6ull  * 1024 * 1024)
#define OFF_TR  (8ull  * 1024 * 1024)
#define OFF_FF  (10ull * 1024 * 1024)
#define OFF_GF  (12ull * 1024 * 1024)
#define OFF_FR  (14ull * 1024 * 1024)
#define OFF_GR  (16ull * 1024 * 1024)
#define OFF_Z   (18ull * 1024 * 1024)   // 4M floats: [b][q][k] mask logits
#define OFF_ST  (22ull * 1024 * 1024)   // 4*32768 floats: mf, rsf, mr, rsr
#define OFF_AT  (23ull * 1024 * 1024)   // 32M floats: [b*8+h][q][k]

__device__ float g_scratch[56ull * 1024ull * 1024ull];

// ---------------------------------------------------------------------------
// Generic C = A(MxK) @ B(KxN) + bias,  64x64 block tile, 4x4 per thread.
// All dims multiples of 64 / K multiple of 16 (guaranteed here).
// ---------------------------------------------------------------------------
__global__ __launch_bounds__(NT)
void gemm_bias_kernel(const float* __restrict__ A,
                      const float* __restrict__ Bm,
                      const float* __restrict__ bias,
                      float* __restrict__ C,
                      int K, int lda, int ldb, int ldc)
{
    __shared__ float As[16][64];
    __shared__ float Bs[16][64];

    const int tid = threadIdx.x;
    const int tx  = tid & 15;
    const int ty  = tid >> 4;
    const int m0  = blockIdx.y * 64;
    const int n0  = blockIdx.x * 64;

    const int ar = tid >> 2;         // 0..63
    const int ac = (tid & 3) * 4;    // 0,4,8,12
    const int br = tid >> 4;         // 0..15
    const int bc = (tid & 15) * 4;   // 0..60

    const float* Ap = A  + (size_t)(m0 + ar) * lda + ac;
    const float* Bp = Bm + (size_t)br * ldb + n0 + bc;

    float acc[4][4] = {};

    for (int k0 = 0; k0 < K; k0 += 16) {
        float4 a4 = *(const float4*)(Ap + k0);
        float4 b4 = *(const float4*)(Bp + (size_t)k0 * ldb);
        As[ac + 0][ar] = a4.x;
        As[ac + 1][ar] = a4.y;
        As[ac + 2][ar] = a4.z;
        As[ac + 3][ar] = a4.w;
        *(float4*)&Bs[br][bc] = b4;
        __syncthreads();
#pragma unroll
        for (int k = 0; k < 16; ++k) {
            float4 a = *(const float4*)&As[k][ty * 4];
            float4 b = *(const float4*)&Bs[k][tx * 4];
            float av[4] = {a.x, a.y, a.z, a.w};
            float bv[4] = {b.x, b.y, b.z, b.w};
#pragma unroll
            for (int i = 0; i < 4; ++i)
#pragma unroll
                for (int j = 0; j < 4; ++j)
                    acc[i][j] = fmaf(av[i], bv[j], acc[i][j]);
        }
        __syncthreads();
    }

    float4 bb = *(const float4*)(bias + n0 + tx * 4);
#pragma unroll
    for (int i = 0; i < 4; ++i) {
        float4 r;
        r.x = acc[i][0] + bb.x;
        r.y = acc[i][1] + bb.y;
        r.z = acc[i][2] + bb.z;
        r.w = acc[i][3] + bb.w;
        *(float4*)&C[(size_t)(m0 + ty * 4 + i) * ldc + n0 + tx * 4] = r;
    }
}

// ---------------------------------------------------------------------------
// scores: per (b,h):  C[i][j] = 0.125 * sum_d q[i,d] k[j,d]
// q,k are [4096][512] row-major, head h occupies cols h*64..h*64+63
// ---------------------------------------------------------------------------
__global__ __launch_bounds__(NT)
void scores_kernel(const float* __restrict__ qg,
                   const float* __restrict__ kg,
                   float* __restrict__ At)
{
    const int bh = blockIdx.z;
    const int b  = bh >> 3, h = bh & 7;
    const float* A  = qg + (size_t)b * 1024 * 512 + h * 64;
    const float* Bm = kg + (size_t)b * 1024 * 512 + h * 64;
    float* C = At + (size_t)bh * 1024 * 1024;

    __shared__ float As[16][64];
    __shared__ float Bs[16][64];

    const int tid = threadIdx.x;
    const int tx  = tid & 15;
    const int ty  = tid >> 4;
    const int m0  = blockIdx.y * 64;
    const int n0  = blockIdx.x * 64;

    const int ar = tid >> 2;
    const int ac = (tid & 3) * 4;

    const float* Ap = A  + (size_t)(m0 + ar) * 512 + ac;
    const float* Bp = Bm + (size_t)(n0 + ar) * 512 + ac;

    float acc[4][4] = {};

    for (int k0 = 0; k0 < 64; k0 += 16) {
        float4 a4 = *(const float4*)(Ap + k0);
        float4 b4 = *(const float4*)(Bp + k0);
        As[ac + 0][ar] = a4.x; As[ac + 1][ar] = a4.y;
        As[ac + 2][ar] = a4.z; As[ac + 3][ar] = a4.w;
        Bs[ac + 0][ar] = b4.x; Bs[ac + 1][ar] = b4.y;
        Bs[ac + 2][ar] = b4.z; Bs[ac + 3][ar] = b4.w;
        __syncthreads();
#pragma unroll
        for (int k = 0; k < 16; ++k) {
            float4 a = *(const float4*)&As[k][ty * 4];
            float4 b = *(const float4*)&Bs[k][tx * 4];
            float av[4] = {a.x, a.y, a.z, a.w};
            float bv[4] = {b.x, b.y, b.z, b.w};
#pragma unroll
            for (int i = 0; i < 4; ++i)
#pragma unroll
                for (int j = 0; j < 4; ++j)
                    acc[i][j] = fmaf(av[i], bv[j], acc[i][j]);
        }
        __syncthreads();
    }

#pragma unroll
    for (int i = 0; i < 4; ++i) {
        float4 r;
        r.x = acc[i][0] * 0.125f;
        r.y = acc[i][1] * 0.125f;
        r.z = acc[i][2] * 0.125f;
        r.w = acc[i][3] * 0.125f;
        *(float4*)&C[(size_t)(m0 + ty * 4 + i) * 1024 + n0 + tx * 4] = r;
    }
}

// ---------------------------------------------------------------------------
// in-place row softmax over 1024 elements; one block per row
// ---------------------------------------------------------------------------
__global__ __launch_bounds__(NT)
void softmax_kernel(float* __restrict__ At)
{
    const size_t row = blockIdx.x;
    float4* p = (float4*)(At + row * 1024);
    const int tid = threadIdx.x;

    float4 v = p[tid];
    __shared__ float red[NT];
    float m = fmaxf(fmaxf(v.x, v.y), fmaxf(v.z, v.w));
    red[tid] = m;
    __syncthreads();
    for (int s = 128; s > 0; s >>= 1) {
        if (tid < s) red[tid] = fmaxf(red[tid], red[tid + s]);
        __syncthreads();
    }
    m = red[0];
    __syncthreads();

    float4 e;
    e.x = __expf(v.x - m);
    e.y = __expf(v.y - m);
    e.z = __expf(v.z - m);
    e.w = __expf(v.w - m);
    red[tid] = e.x + e.y + e.z + e.w;
    __syncthreads();
    for (int s = 128; s > 0; s >>= 1) {
        if (tid < s) red[tid] += red[tid + s];
        __syncthreads();
    }
    float inv = 1.0f / red[0];
    e.x *= inv; e.y *= inv; e.z *= inv; e.w *= inv;
    p[tid] = e;
}

// ---------------------------------------------------------------------------
// z[b][q][k] = sum_h At[(b*8+h)][q][k]*cw[h] + cb   (mask logit)
// ---------------------------------------------------------------------------
__global__ __launch_bounds__(NT)
void z_kernel(const float* __restrict__ At,
              const float* __restrict__ cw,
              const float* __restrict__ cbp,
              float* __restrict__ z)
{
    const size_t i4  = (size_t)blockIdx.x * NT + threadIdx.x;  // float4 index
    const size_t b   = i4 >> 18;          // 262144 float4 per batch plane
    const size_t qk4 = i4 & 262143;
    const float cb = cbp[0];
    const float4* base = (const float4*)At + b * (8ull * 262144) + qk4;
    float4 acc = make_float4(cb, cb, cb, cb);
#pragma unroll
    for (int h = 0; h < 8; ++h) {
        float w   = cw[h];
        float4 a  = base[(size_t)h * 262144];
        acc.x = fmaf(a.x, w, acc.x);
        acc.y = fmaf(a.y, w, acc.y);
        acc.z = fmaf(a.z, w, acc.z);
        acc.w = fmaf(a.w, w, acc.w);
    }
    ((float4*)z)[i4] = acc;
}

// ---------------------------------------------------------------------------
// per-row stats of softmax(A_t*M_f) / softmax(A_t*M_r):
//   masked entries have value 0 (contribute exp(0-m))
//   stats: [0..32767]=mf  [+32768]=1/sf  [+65536]=mr  [+98304]=1/sr
// ---------------------------------------------------------------------------
__global__ __launch_bounds__(NT)
void stats_kernel(const float* __restrict__ At,
                  const float* __restrict__ z,
                  float* __restrict__ stats)
{
    const int row = blockIdx.x;            // (b*8+h)*1024 + q
    const int b   = row >> 13;
    const int q   = row & 1023;
    const float4* ap = (const float4*)(At + (size_t)row * 1024);
    const float4* zp = (const float4*)(z + (((size_t)b << 10) + q) * 1024);
    const int tid = threadIdx.x;

    float4 a  = ap[tid];
    float4 zz = zp[tid];
    float av[4] = {a.x, a.y, a.z, a.w};
    float zv[4] = {zz.x, zz.y, zz.z, zz.w};
    float vf[4], vr[4];
    float mf = 0.f, mr = 0.f;
#pragma unroll
    for (int j = 0; j < 4; ++j) {
        vf[j] = (zv[j] <= 0.f) ? av[j] : 0.f;
        vr[j] = (zv[j] >= 0.f) ? av[j] : 0.f;
        mf = fmaxf(mf, vf[j]);
        mr = fmaxf(mr, vr[j]);
    }

    __shared__ float rf[NT], rr[NT];
    rf[tid] = mf; rr[tid] = mr;
    __syncthreads();
    for (int s = 128; s > 0; s >>= 1) {
        if (tid < s) {
            rf[tid] = fmaxf(rf[tid], rf[tid + s]);
            rr[tid] = fmaxf(rr[tid], rr[tid + s]);
        }
        __syncthreads();
    }
    mf = rf[0]; mr = rr[0];
    __syncthreads();

    float sf = 0.f, sr = 0.f;
#pragma unroll
    for (int j = 0; j < 4; ++j) {
        sf += __expf(vf[j] - mf);
        sr += __expf(vr[j] - mr);
    }
    rf[tid] = sf; rr[tid] = sr;
    __syncthreads();
    for (int s = 128; s > 0; s >>= 1) {
        if (tid < s) { rf[tid] += rf[tid + s]; rr[tid] += rr[tid + s]; }
        __syncthreads();
    }
    if (tid == 0) {
        stats[row]          = mf;
        stats[32768 + row]  = 1.0f / rf[0];
        stats[65536 + row]  = mr;
        stats[98304 + row]  = 1.0f / rr[0];
    }
}

// ---------------------------------------------------------------------------
// AV: per (b,h):  T_f = A_f @ v, T_r = A_r @ v,  64 q-rows per block
// A_f[i][k] = exp( (z<=0 ? a : 0) - mf[i] ) * rsf[i]   (regenerated on the fly)
// ---------------------------------------------------------------------------
__global__ __launch_bounds__(NT)
void av_kernel(const float* __restrict__ At,
               const float* __restrict__ z,
               const float* __restrict__ stats,
               const float* __restrict__ vg,
               float* __restrict__ Tf,
               float* __restrict__ Tr)
{
    const int bh = blockIdx.y;
    const int b  = bh >> 3, h = bh & 7;
    const int q0 = blockIdx.x * 64;

    __shared__ float Af[16][64];
    __shared__ float Ar[16][64];
    __shared__ float Vs[16][64];
    __shared__ float smf[64], srf[64], smr[64], srr[64];

    const int tid = threadIdx.x;
    const int tx  = tid & 15;
    const int ty  = tid >> 4;

    const int rowg = bh * 1024 + q0;
    if (tid < 64) {
        smf[tid] = stats[rowg + tid];
        srf[tid] = stats[32768 + rowg + tid];
        smr[tid] = stats[65536 + rowg + tid];
        srr[tid] = stats[98304 + rowg + tid];
    }
    __syncthreads();

    const int ai = tid >> 2;         // q-row within tile (0..63)
    const int ac = (tid & 3) * 4;    // k within 16-tile
    const float mf = smf[ai], rf = srf[ai];
    const float mr = smr[ai], rr = srr[ai];

    const float* ap = At + (size_t)bh * 1048576 + (size_t)(q0 + ai) * 1024 + ac;
    const float* zp = z + ((size_t)b * 1024 + q0 + ai) * 1024 + ac;
    const float* vp = vg + ((size_t)b * 1024 + (tid >> 4)) * 512 + h * 64 + (tid & 15) * 4;

    float accf[4][4] = {};
    float accr[4][4] = {};

    for (int k0 = 0; k0 < 1024; k0 += 16) {
        float4 a4 = *(const float4*)(ap + k0);
        float4 z4 = *(const float4*)(zp + k0);
        float4 v4 = *(const float4*)(vp + (size_t)k0 * 512);
        float av[4] = {a4.x, a4.y, a4.z, a4.w};
        float zv[4] = {z4.x, z4.y, z4.z, z4.w};
#pragma unroll
        for (int j = 0; j < 4; ++j) {
            float vfj = (zv[j] <= 0.f) ? av[j] : 0.f;
            float vrj = (zv[j] >= 0.f) ? av[j] : 0.f;
            Af[ac + j][ai] = __expf(vfj - mf) * rf;
            Ar[ac + j][ai] = __expf(vrj - mr) * rr;
        }
        *(float4*)&Vs[tid >> 4][(tid & 15) * 4] = v4;
        __syncthreads();
#pragma unroll
        for (int k = 0; k < 16; ++k) {
            float4 fa = *(const float4*)&Af[k][ty * 4];
            float4 ra = *(const float4*)&Ar[k][ty * 4];
            float4 vb = *(const float4*)&Vs[k][tx * 4];
            float fav[4] = {fa.x, fa.y, fa.z, fa.w};
            float rav[4] = {ra.x, ra.y, ra.z, ra.w};
            float vbv[4] = {vb.x, vb.y, vb.z, vb.w};
#pragma unroll
            for (int i = 0; i < 4; ++i)
#pragma unroll
                for (int j = 0; j < 4; ++j) {
                    accf[i][j] = fmaf(fav[i], vbv[j], accf[i][j]);
                    accr[i][j] = fmaf(rav[i], vbv[j], accr[i][j]);
                }
        }
        __syncthreads();
    }

#pragma unroll
    for (int i = 0; i < 4; ++i) {
        size_t o = ((size_t)b * 1024 + q0 + ty * 4 + i) * 512 + h * 64 + tx * 4;
        float4 rA = {accf[i][0], accf[i][1], accf[i][2], accf[i][3]};
        float4 rB = {accr[i][0], accr[i][1], accr[i][2], accr[i][3]};
        *(float4*)&Tf[o] = rA;
        *(float4*)&Tr[o] = rB;
    }
}

// ---------------------------------------------------------------------------
// out = F_f * w + F_r * (1-w),  w = sigmoid(sigmoid(G_f) - sigmoid(G_r))
// ---------------------------------------------------------------------------
__global__ __launch_bounds__(NT)
void combine_kernel(const float* __restrict__ Ff, const float* __restrict__ Gf,
                    const float* __restrict__ Fr, const float* __restrict__ Gr,
                    float* __restrict__ out)
{
    const size_t i4 = (size_t)blockIdx.x * NT + threadIdx.x;
    float4 ff = ((const float4*)Ff)[i4];
    float4 gf = ((const float4*)Gf)[i4];
    float4 fr = ((const float4*)Fr)[i4];
    float4 gr = ((const float4*)Gr)[i4];

    float ffv[4] = {ff.x, ff.y, ff.z, ff.w};
    float gfv[4] = {gf.x, gf.y, gf.z, gf.w};
    float frv[4] = {fr.x, fr.y, fr.z, fr.w};
    float grv[4] = {gr.x, gr.y, gr.z, gr.w};
    float ov[4];
#pragma unroll
    for (int j = 0; j < 4; ++j) {
        float sgf = 1.0f / (1.0f + __expf(-gfv[j]));
        float sgr = 1.0f / (1.0f + __expf(-grv[j]));
        float w   = 1.0f / (1.0f + __expf(sgr - sgf));
        ov[j] = ffv[j] * w + frv[j] * (1.0f - w);
    }
    float4 o = {ov[0], ov[1], ov[2], ov[3]};
    ((float4*)out)[i4] = o;
}

// ---------------------------------------------------------------------------
extern "C" void kernel_launch(void* const* d_in, const int* in_sizes, int n_in,
                              void* d_out, int out_size)
{
    const float* x   = (const float*)d_in[0];
    const float* Wq  = (const float*)d_in[1];
    const float* bq  = (const float*)d_in[2];
    const float* Wk  = (const float*)d_in[3];
    const float* bk  = (const float*)d_in[4];
    const float* Wv  = (const float*)d_in[5];
    const float* bv  = (const float*)d_in[6];
    const float* cw  = (const float*)d_in[7];
    const float* cb  = (const float*)d_in[8];
    const float* Wfh = (const float*)d_in[9];
    const float* bfh = (const float*)d_in[10];
    const float* Wfg = (const float*)d_in[11];
    const float* bfg = (const float*)d_in[12];
    const float* Wrh = (const float*)d_in[13];
    const float* brh = (const float*)d_in[14];
    const float* Wrg = (const float*)d_in[15];
    const float* brg = (const float*)d_in[16];
    float* out = (float*)d_out;

    float* s = nullptr;
    cudaGetSymbolAddress((void**)&s, g_scratch);

    float* q     = s + OFF_Q;
    float* k     = s + OFF_K;
    float* v     = s + OFF_V;
    float* Tf    = s + OFF_TF;
    float* Tr    = s + OFF_TR;
    float* Ff    = s + OFF_FF;
    float* Gf    = s + OFF_GF;
    float* Fr    = s + OFF_FR;
    float* Gr    = s + OFF_GR;
    float* z     = s + OFF_Z;
    float* stats = s + OFF_ST;
    float* At    = s + OFF_AT;

    dim3 gProj(8, 64);   // N/64=8, M/64=64

    gemm_bias_kernel<<<gProj, NT>>>(x, Wq, bq, q, 512, 512, 512, 512);
    gemm_bias_kernel<<<gProj, NT>>>(x, Wk, bk, k, 512, 512, 512, 512);
    gemm_bias_kernel<<<gProj, NT>>>(x, Wv, bv, v, 512, 512, 512, 512);

    scores_kernel<<<dim3(16, 16, 32), NT>>>(q, k, At);
    softmax_kernel<<<32768, NT>>>(At);
    z_kernel<<<4096, NT>>>(At, cw, cb, z);
    stats_kernel<<<32768, NT>>>(At, z, stats);
    av_kernel<<<dim3(16, 32), NT>>>(At, z, stats, v, Tf, Tr);

    gemm_bias_kernel<<<gProj, NT>>>(Tf, Wfh, bfh, Ff, 512, 512, 512, 512);
    gemm_bias_kernel<<<gProj, NT>>>(Tf, Wfg, bfg, Gf, 512, 512, 512, 512);
    gemm_bias_kernel<<<gProj, NT>>>(Tr, Wrh, brh, Fr, 512, 512, 512, 512);
    gemm_bias_kernel<<<gProj, NT>>>(Tr, Wrg, brg, Gr, 512, 512, 512, 512);

    combine_kernel<<<2048, NT>>>(Ff, Gf, Fr, Gr, out);
}

// round 2
// speedup vs baseline: 1.4361x; 1.4361x over previous
#include <cuda_runtime.h>
#include <cstdint>

// ---------------------------------------------------------------------------
// ComplementaryAttention  B=4 T=1024 D=512 H=8 hd=64   (round 2: fused + 128x64)
//
//   1. q,k,v = x @ W + b                         (3x gemm_bias, 128x64 tiles)
//   2. raw scores -> At                          (scores_kernel)
//   3. fused: softmax(At), z=sum_h a*cw+cb, masks(z sign), t=exp(a),
//      rsf=1/sum(mask_f? t:1), rsr likewise; At <- t, maskbuf <- 2-bit masks
//   4. av: Tf = [(mf? t:1) @ v]*rsf, Tr likewise  (pure select+FMA gemm)
//   5. F/G gemms (4x), combine
// ---------------------------------------------------------------------------

#define NT 256

#define OFF_Q   (0ull)
#define OFF_K   (2ull  * 1024 * 1024)
#define OFF_V   (4ull  * 1024 * 1024)
#define OFF_TF  (6ull  * 1024 * 1024)
#define OFF_TR  (8ull  * 1024 * 1024)
#define OFF_FF  (10ull * 1024 * 1024)
#define OFF_GF  (12ull * 1024 * 1024)
#define OFF_FR  (14ull * 1024 * 1024)
#define OFF_GR  (16ull * 1024 * 1024)
#define OFF_MB  (18ull * 1024 * 1024)   // mask bytes (4M bytes, reinterpreted)
#define OFF_ST  (22ull * 1024 * 1024)   // stats: [0..32767]=rsf, [32768..]=rsr
#define OFF_AT  (23ull * 1024 * 1024)   // 32M floats

__device__ float g_scratch[56ull * 1024ull * 1024ull];

// ---------------------------------------------------------------------------
// C = A(MxK) @ B(KxN) + bias.  128x64 tile, 8x4/thread, reg-prefetch.
// ---------------------------------------------------------------------------
__global__ __launch_bounds__(NT)
void gemm_bias_kernel(const float* __restrict__ A,
                      const float* __restrict__ Bm,
                      const float* __restrict__ bias,
                      float* __restrict__ C,
                      int K, int lda, int ldb, int ldc)
{
    __shared__ float As[16][128];
    __shared__ float Bs[16][64];

    const int tid = threadIdx.x;
    const int m0  = blockIdx.y * 128;
    const int n0  = blockIdx.x * 64;
    const int ar  = tid >> 1;        // 0..127
    const int ac  = (tid & 1) * 8;   // 0 or 8
    const int br  = tid >> 4;        // 0..15
    const int bc  = (tid & 15) * 4;  // 0..60
    const int tx  = tid & 15;
    const int ty  = tid >> 4;

    const float* Ap = A  + (size_t)(m0 + ar) * lda + ac;
    const float* Bp = Bm + (size_t)br * ldb + n0 + bc;

    float4 a0 = *(const float4*)(Ap);
    float4 a1 = *(const float4*)(Ap + 4);
    float4 b0 = *(const float4*)(Bp);

    float acc[8][4] = {};

    for (int k0 = 0; k0 < K; k0 += 16) {
        As[ac + 0][ar] = a0.x; As[ac + 1][ar] = a0.y;
        As[ac + 2][ar] = a0.z; As[ac + 3][ar] = a0.w;
        As[ac + 4][ar] = a1.x; As[ac + 5][ar] = a1.y;
        As[ac + 6][ar] = a1.z; As[ac + 7][ar] = a1.w;
        *(float4*)&Bs[br][bc] = b0;
        __syncthreads();
        if (k0 + 16 < K) {
            a0 = *(const float4*)(Ap + k0 + 16);
            a1 = *(const float4*)(Ap + k0 + 20);
            b0 = *(const float4*)(Bp + (size_t)(k0 + 16) * ldb);
        }
#pragma unroll
        for (int k = 0; k < 16; ++k) {
            float4 x0 = *(const float4*)&As[k][ty * 8];
            float4 x1 = *(const float4*)&As[k][ty * 8 + 4];
            float4 y  = *(const float4*)&Bs[k][tx * 4];
            float xa[8] = {x0.x, x0.y, x0.z, x0.w, x1.x, x1.y, x1.z, x1.w};
            float yb[4] = {y.x, y.y, y.z, y.w};
#pragma unroll
            for (int i = 0; i < 8; ++i)
#pragma unroll
                for (int j = 0; j < 4; ++j)
                    acc[i][j] = fmaf(xa[i], yb[j], acc[i][j]);
        }
        __syncthreads();
    }

    float4 bb = *(const float4*)(bias + n0 + tx * 4);
#pragma unroll
    for (int i = 0; i < 8; ++i) {
        float4 r;
        r.x = acc[i][0] + bb.x; r.y = acc[i][1] + bb.y;
        r.z = acc[i][2] + bb.z; r.w = acc[i][3] + bb.w;
        *(float4*)&C[(size_t)(m0 + ty * 8 + i) * ldc + n0 + tx * 4] = r;
    }
}

// ---------------------------------------------------------------------------
// scores: per (b,h):  C[i][j] = 0.125 * sum_d q[i,d] k[j,d]   (128x64, K=64)
// ---------------------------------------------------------------------------
__global__ __launch_bounds__(NT)
void scores_kernel(const float* __restrict__ qg,
                   const float* __restrict__ kg,
                   float* __restrict__ At)
{
    const int bh = blockIdx.z;
    const int b  = bh >> 3, h = bh & 7;
    const float* A  = qg + (size_t)b * 524288 + h * 64;
    const float* Bm = kg + (size_t)b * 524288 + h * 64;
    float* C = At + (size_t)bh * 1048576;

    __shared__ float As[16][128];
    __shared__ float Bs[16][64];

    const int tid = threadIdx.x;
    const int m0  = blockIdx.y * 128;
    const int n0  = blockIdx.x * 64;
    const int ar  = tid >> 1;
    const int ac  = (tid & 1) * 8;
    const int br  = tid >> 2;        // 0..63 (n within tile)
    const int bq2 = (tid & 3) * 4;   // 0,4,8,12 (k within 16)
    const int tx  = tid & 15;
    const int ty  = tid >> 4;

    const float* Ap = A  + (size_t)(m0 + ar) * 512 + ac;
    const float* Bp = Bm + (size_t)(n0 + br) * 512 + bq2;

    float4 a0 = *(const float4*)(Ap);
    float4 a1 = *(const float4*)(Ap + 4);
    float4 b0 = *(const float4*)(Bp);

    float acc[8][4] = {};

    for (int k0 = 0; k0 < 64; k0 += 16) {
        As[ac + 0][ar] = a0.x; As[ac + 1][ar] = a0.y;
        As[ac + 2][ar] = a0.z; As[ac + 3][ar] = a0.w;
        As[ac + 4][ar] = a1.x; As[ac + 5][ar] = a1.y;
        As[ac + 6][ar] = a1.z; As[ac + 7][ar] = a1.w;
        Bs[bq2 + 0][br] = b0.x; Bs[bq2 + 1][br] = b0.y;
        Bs[bq2 + 2][br] = b0.z; Bs[bq2 + 3][br] = b0.w;
        __syncthreads();
        if (k0 + 16 < 64) {
            a0 = *(const float4*)(Ap + k0 + 16);
            a1 = *(const float4*)(Ap + k0 + 20);
            b0 = *(const float4*)(Bp + k0 + 16);
        }
#pragma unroll
        for (int k = 0; k < 16; ++k) {
            float4 x0 = *(const float4*)&As[k][ty * 8];
            float4 x1 = *(const float4*)&As[k][ty * 8 + 4];
            float4 y  = *(const float4*)&Bs[k][tx * 4];
            float xa[8] = {x0.x, x0.y, x0.z, x0.w, x1.x, x1.y, x1.z, x1.w};
            float yb[4] = {y.x, y.y, y.z, y.w};
#pragma unroll
            for (int i = 0; i < 8; ++i)
#pragma unroll
                for (int j = 0; j < 4; ++j)
                    acc[i][j] = fmaf(xa[i], yb[j], acc[i][j]);
        }
        __syncthreads();
    }

#pragma unroll
    for (int i = 0; i < 8; ++i) {
        float4 r;
        r.x = acc[i][0] * 0.125f; r.y = acc[i][1] * 0.125f;
        r.z = acc[i][2] * 0.125f; r.w = acc[i][3] * 0.125f;
        *(float4*)&C[(size_t)(m0 + ty * 8 + i) * 1024 + n0 + tx * 4] = r;
    }
}

// ---------------------------------------------------------------------------
// fused: per (b,q), all 8 heads.
//   a    = softmax(scores)  (per head, max-subtracted)
//   z    = sum_h a*cw[h] + cb ; mask_f = z<=0, mask_r = z>=0
//   t    = exp(a)            (written back to At)
//   rsf  = 1/sum_k (mask_f ? t : 1), rsr likewise  (m=0 masked softmax)
// ---------------------------------------------------------------------------
__device__ __forceinline__ float warpMaxF(float v) {
#pragma unroll
    for (int o = 16; o; o >>= 1) v = fmaxf(v, __shfl_xor_sync(0xffffffffu, v, o));
    return v;
}
__device__ __forceinline__ float warpSumF(float v) {
#pragma unroll
    for (int o = 16; o; o >>= 1) v += __shfl_xor_sync(0xffffffffu, v, o);
    return v;
}

__global__ __launch_bounds__(NT)
void fused_sm_kernel(float* __restrict__ At,
                     const float* __restrict__ cw,
                     const float* __restrict__ cbp,
                     unsigned char* __restrict__ maskbuf,
                     float* __restrict__ stats)
{
    const int bq = blockIdx.x;      // b*1024 + q
    const int b  = bq >> 10;
    const int q  = bq & 1023;
    const int tid  = threadIdx.x;
    const int lane = tid & 31, wid = tid >> 5;

    __shared__ float red[16][8];
    __shared__ float fin[16];

    const float cb = cbp[0];
    const size_t rowbase = ((size_t)q << 10) + (size_t)tid * 4;

    float a[8][4];
    float lm[8];
#pragma unroll
    for (int h = 0; h < 8; ++h) {
        float4 v = *(const float4*)(At + (size_t)(b * 8 + h) * 1048576 + rowbase);
        a[h][0] = v.x; a[h][1] = v.y; a[h][2] = v.z; a[h][3] = v.w;
        lm[h] = fmaxf(fmaxf(v.x, v.y), fmaxf(v.z, v.w));
    }
    // batched max reduce
#pragma unroll
    for (int h = 0; h < 8; ++h) {
        float w = warpMaxF(lm[h]);
        if (lane == 0) red[h][wid] = w;
    }
    __syncthreads();
    if (tid < 8) {
        float m = red[tid][0];
#pragma unroll
        for (int i = 1; i < 8; ++i) m = fmaxf(m, red[tid][i]);
        fin[tid] = m;
    }
    __syncthreads();
    float ls[8];
#pragma unroll
    for (int h = 0; h < 8; ++h) {
        float m = fin[h];
        float s = 0.f;
#pragma unroll
        for (int j = 0; j < 4; ++j) {
            a[h][j] = __expf(a[h][j] - m);
            s += a[h][j];
        }
        ls[h] = s;
    }
    __syncthreads();
#pragma unroll
    for (int h = 0; h < 8; ++h) {
        float w = warpSumF(ls[h]);
        if (lane == 0) red[h][wid] = w;
    }
    __syncthreads();
    if (tid < 8) {
        float s = red[tid][0];
#pragma unroll
        for (int i = 1; i < 8; ++i) s += red[tid][i];
        fin[tid] = 1.0f / s;
    }
    __syncthreads();

    // normalize + z
    float zacc[4] = {cb, cb, cb, cb};
#pragma unroll
    for (int h = 0; h < 8; ++h) {
        float inv = fin[h];
        float w   = cw[h];
#pragma unroll
        for (int j = 0; j < 4; ++j) {
            a[h][j] *= inv;
            zacc[j] = fmaf(a[h][j], w, zacc[j]);
        }
    }
    unsigned mby[4];
#pragma unroll
    for (int j = 0; j < 4; ++j) {
        unsigned mf = (zacc[j] <= 0.f) ? 1u : 0u;
        unsigned mr = (zacc[j] >= 0.f) ? 2u : 0u;
        mby[j] = mf | mr;
    }

    // t = exp(a); masked sums (m = 0)
    float lsf[8], lsr[8];
#pragma unroll
    for (int h = 0; h < 8; ++h) {
        float sf = 0.f, sr = 0.f;
#pragma unroll
        for (int j = 0; j < 4; ++j) {
            float t = __expf(a[h][j]);
            a[h][j] = t;
            sf += (mby[j] & 1u) ? t : 1.0f;
            sr += (mby[j] & 2u) ? t : 1.0f;
        }
        lsf[h] = sf; lsr[h] = sr;
    }
    __syncthreads();
#pragma unroll
    for (int h = 0; h < 8; ++h) {
        float w = warpSumF(lsf[h]);
        if (lane == 0) red[h][wid] = w;
        w = warpSumF(lsr[h]);
        if (lane == 0) red[8 + h][wid] = w;
    }
    __syncthreads();
    if (tid < 16) {
        float s = red[tid][0];
#pragma unroll
        for (int i = 1; i < 8; ++i) s += red[tid][i];
        float inv = 1.0f / s;
        int h = tid & 7;
        int row = (b * 8 + h) * 1024 + q;
        if (tid < 8) stats[row] = inv;
        else         stats[32768 + row] = inv;
    }

    // write back t and mask bytes
#pragma unroll
    for (int h = 0; h < 8; ++h) {
        float4 v = {a[h][0], a[h][1], a[h][2], a[h][3]};
        *(float4*)(At + (size_t)(b * 8 + h) * 1048576 + rowbase) = v;
    }
    uchar4 m4 = {(unsigned char)mby[0], (unsigned char)mby[1],
                 (unsigned char)mby[2], (unsigned char)mby[3]};
    *(uchar4*)(maskbuf + (size_t)bq * 1024 + tid * 4) = m4;
}

// ---------------------------------------------------------------------------
// av: per (b,h): Tf = [(mf? t:1) @ v]*rsf, Tr = [(mr? t:1) @ v]*rsr
// 128x64 tile (q x d), K=1024, dual 8x4 accumulators, no exp in hot loop.
// ---------------------------------------------------------------------------
__global__ __launch_bounds__(NT)
void av_kernel(const float* __restrict__ At,
               const unsigned char* __restrict__ maskb,
               const float* __restrict__ stats,
               const float* __restrict__ vg,
               float* __restrict__ Tf,
               float* __restrict__ Tr)
{
    const int bh = blockIdx.y;
    const int b  = bh >> 3, h = bh & 7;
    const int q0 = blockIdx.x * 128;

    __shared__ float Af[16][128];
    __shared__ float Ar[16][128];
    __shared__ float Vs[16][64];
    __shared__ float ssf[128], ssr[128];

    const int tid = threadIdx.x;
    if (tid < 128) {
        ssf[tid] = stats[bh * 1024 + q0 + tid];
        ssr[tid] = stats[32768 + bh * 1024 + q0 + tid];
    }

    const int ar = tid >> 1;
    const int ac = (tid & 1) * 8;
    const int vr = tid >> 4;
    const int vc = (tid & 15) * 4;
    const int tx = tid & 15;
    const int ty = tid >> 4;

    const float* tp = At + (size_t)bh * 1048576 + (size_t)(q0 + ar) * 1024 + ac;
    const unsigned char* mp = maskb + (((size_t)b << 10) + q0 + ar) * 1024 + ac;
    const float* vp = vg + (((size_t)b << 10) + vr) * 512 + h * 64 + vc;

    float4 t0 = *(const float4*)(tp);
    float4 t1 = *(const float4*)(tp + 4);
    uint2  mk = *(const uint2*)(mp);
    float4 v4 = *(const float4*)(vp);

    float accf[8][4] = {};
    float accr[8][4] = {};

    for (int k0 = 0; k0 < 1024; k0 += 16) {
        float tv[8] = {t0.x, t0.y, t0.z, t0.w, t1.x, t1.y, t1.z, t1.w};
        unsigned mb[8];
#pragma unroll
        for (int j = 0; j < 4; ++j) {
            mb[j]     = (mk.x >> (8 * j)) & 3u;
            mb[4 + j] = (mk.y >> (8 * j)) & 3u;
        }
#pragma unroll
        for (int j = 0; j < 8; ++j) {
            Af[ac + j][ar] = (mb[j] & 1u) ? tv[j] : 1.0f;
            Ar[ac + j][ar] = (mb[j] & 2u) ? tv[j] : 1.0f;
        }
        *(float4*)&Vs[vr][vc] = v4;
        __syncthreads();
        if (k0 + 16 < 1024) {
            t0 = *(const float4*)(tp + k0 + 16);
            t1 = *(const float4*)(tp + k0 + 20);
            mk = *(const uint2*)(mp + k0 + 16);
            v4 = *(const float4*)(vp + (size_t)(k0 + 16) * 512);
        }
#pragma unroll
        for (int k = 0; k < 16; ++k) {
            float4 f0 = *(const float4*)&Af[k][ty * 8];
            float4 f1 = *(const float4*)&Af[k][ty * 8 + 4];
            float4 r0 = *(const float4*)&Ar[k][ty * 8];
            float4 r1 = *(const float4*)&Ar[k][ty * 8 + 4];
            float4 vb = *(const float4*)&Vs[k][tx * 4];
            float fa[8] = {f0.x, f0.y, f0.z, f0.w, f1.x, f1.y, f1.z, f1.w};
            float ra[8] = {r0.x, r0.y, r0.z, r0.w, r1.x, r1.y, r1.z, r1.w};
            float vv[4] = {vb.x, vb.y, vb.z, vb.w};
#pragma unroll
            for (int i = 0; i < 8; ++i)
#pragma unroll
                for (int j = 0; j < 4; ++j) {
                    accf[i][j] = fmaf(fa[i], vv[j], accf[i][j]);
                    accr[i][j] = fmaf(ra[i], vv[j], accr[i][j]);
                }
        }
        __syncthreads();
    }

#pragma unroll
    for (int i = 0; i < 8; ++i) {
        float rf = ssf[ty * 8 + i];
        float rr = ssr[ty * 8 + i];
        size_t o = (((size_t)b << 10) + q0 + ty * 8 + i) * 512 + h * 64 + tx * 4;
        float4 Rf = {accf[i][0] * rf, accf[i][1] * rf, accf[i][2] * rf, accf[i][3] * rf};
        float4 Rr = {accr[i][0] * rr, accr[i][1] * rr, accr[i][2] * rr, accr[i][3] * rr};
        *(float4*)&Tf[o] = Rf;
        *(float4*)&Tr[o] = Rr;
    }
}

// ---------------------------------------------------------------------------
// out = F_f * w + F_r * (1-w),  w = sigmoid(sigmoid(G_f) - sigmoid(G_r))
// ---------------------------------------------------------------------------
__global__ __launch_bounds__(NT)
void combine_kernel(const float* __restrict__ Ff, const float* __restrict__ Gf,
                    const float* __restrict__ Fr, const float* __restrict__ Gr,
                    float* __restrict__ out)
{
    const size_t i4 = (size_t)blockIdx.x * NT + threadIdx.x;
    float4 ff = ((const float4*)Ff)[i4];
    float4 gf = ((const float4*)Gf)[i4];
    float4 fr = ((const float4*)Fr)[i4];
    float4 gr = ((const float4*)Gr)[i4];

    float ffv[4] = {ff.x, ff.y, ff.z, ff.w};
    float gfv[4] = {gf.x, gf.y, gf.z, gf.w};
    float frv[4] = {fr.x, fr.y, fr.z, fr.w};
    float grv[4] = {gr.x, gr.y, gr.z, gr.w};
    float ov[4];
#pragma unroll
    for (int j = 0; j < 4; ++j) {
        float sgf = 1.0f / (1.0f + __expf(-gfv[j]));
        float sgr = 1.0f / (1.0f + __expf(-grv[j]));
        float w   = 1.0f / (1.0f + __expf(sgr - sgf));
        ov[j] = ffv[j] * w + frv[j] * (1.0f - w);
    }
    float4 o = {ov[0], ov[1], ov[2], ov[3]};
    ((float4*)out)[i4] = o;
}

// ---------------------------------------------------------------------------
extern "C" void kernel_launch(void* const* d_in, const int* in_sizes, int n_in,
                              void* d_out, int out_size)
{
    const float* x   = (const float*)d_in[0];
    const float* Wq  = (const float*)d_in[1];
    const float* bq  = (const float*)d_in[2];
    const float* Wk  = (const float*)d_in[3];
    const float* bk  = (const float*)d_in[4];
    const float* Wv  = (const float*)d_in[5];
    const float* bv  = (const float*)d_in[6];
    const float* cw  = (const float*)d_in[7];
    const float* cb  = (const float*)d_in[8];
    const float* Wfh = (const float*)d_in[9];
    const float* bfh = (const float*)d_in[10];
    const float* Wfg = (const float*)d_in[11];
    const float* bfg = (const float*)d_in[12];
    const float* Wrh = (const float*)d_in[13];
    const float* brh = (const float*)d_in[14];
    const float* Wrg = (const float*)d_in[15];
    const float* brg = (const float*)d_in[16];
    float* out = (float*)d_out;

    float* s = nullptr;
    cudaGetSymbolAddress((void**)&s, g_scratch);

    float* q     = s + OFF_Q;
    float* k     = s + OFF_K;
    float* v     = s + OFF_V;
    float* Tf    = s + OFF_TF;
    float* Tr    = s + OFF_TR;
    float* Ff    = s + OFF_FF;
    float* Gf    = s + OFF_GF;
    float* Fr    = s + OFF_FR;
    float* Gr    = s + OFF_GR;
    unsigned char* maskb = (unsigned char*)(s + OFF_MB);
    float* stats = s + OFF_ST;
    float* At    = s + OFF_AT;

    dim3 gProj(8, 32);   // N/64=8, M/128=32

    gemm_bias_kernel<<<gProj, NT>>>(x, Wq, bq, q, 512, 512, 512, 512);
    gemm_bias_kernel<<<gProj, NT>>>(x, Wk, bk, k, 512, 512, 512, 512);
    gemm_bias_kernel<<<gProj, NT>>>(x, Wv, bv, v, 512, 512, 512, 512);

    scores_kernel<<<dim3(16, 8, 32), NT>>>(q, k, At);
    fused_sm_kernel<<<4096, NT>>>(At, cw, cb, maskb, stats);
    av_kernel<<<dim3(8, 32), NT>>>(At, maskb, stats, v, Tf, Tr);

    gemm_bias_kernel<<<gProj, NT>>>(Tf, Wfh, bfh, Ff, 512, 512, 512, 512);
    gemm_bias_kernel<<<gProj, NT>>>(Tf, Wfg, bfg, Gf, 512, 512, 512, 512);
    gemm_bias_kernel<<<gProj, NT>>>(Tr, Wrh, brh, Fr, 512, 512, 512, 512);
    gemm_bias_kernel<<<gProj, NT>>>(Tr, Wrg, brg, Gr, 512, 512, 512, 512);

    combine_kernel<<<2048, NT>>>(Ff, Gf, Fr, Gr, out);
}

// round 5
// speedup vs baseline: 1.4668x; 1.0213x over previous
#include <cuda_runtime.h>
#include <cuda_bf16.h>
#include <cstdint>

// ---------------------------------------------------------------------------
// ComplementaryAttention  B=4 T=1024 D=512 H=8 hd=64   (round 4: HMMA GEMMs)
//
//   tcgen05 is unavailable (harness PTX target = compute_103, no 'a'), so the
//   7x [4096x512x512] GEMMs use mma.sync.m16n8k16 bf16 with 2-way fp32 split:
//   D = Ah Bh + Al Bh + Ah Bl, fp32 register accum.
// ---------------------------------------------------------------------------

#define NT 256

// fp32 scratch (floats)
#define OFF_Q   (0ull)
#define OFF_K   (2ull  * 1024 * 1024)
#define OFF_V   (4ull  * 1024 * 1024)
#define OFF_FF  (10ull * 1024 * 1024)
#define OFF_GF  (12ull * 1024 * 1024)
#define OFF_FR  (14ull * 1024 * 1024)
#define OFF_GR  (16ull * 1024 * 1024)
#define OFF_MB  (18ull * 1024 * 1024)
#define OFF_ST  (22ull * 1024 * 1024)
#define OFF_AT  (23ull * 1024 * 1024)

__device__ float g_scratch[56ull * 1024ull * 1024ull];

// bf16 scratch (elements)
#define BX_H   (0ull)
#define BX_L   (2ull  * 1024 * 1024)
#define BTF_H  (4ull  * 1024 * 1024)
#define BTF_L  (6ull  * 1024 * 1024)
#define BTR_H  (8ull  * 1024 * 1024)
#define BTR_L  (10ull * 1024 * 1024)
#define BW     (12ull * 1024 * 1024)   // 7 weights * (hi 256K + lo 256K)

__device__ __nv_bfloat16 g_bfbuf[16ull * 1024ull * 1024ull];

// ---------------------------------------------------------------------------
// HMMA m16n8k16 bf16 wrapper
// ---------------------------------------------------------------------------
__device__ __forceinline__ void mma16816(float* c, const uint32_t* a,
                                         const uint32_t* b) {
    asm volatile(
        "mma.sync.aligned.m16n8k16.row.col.f32.bf16.bf16.f32 "
        "{%0,%1,%2,%3}, {%4,%5,%6,%7}, {%8,%9}, {%0,%1,%2,%3};"
        : "+f"(c[0]), "+f"(c[1]), "+f"(c[2]), "+f"(c[3])
        : "r"(a[0]), "r"(a[1]), "r"(a[2]), "r"(a[3]), "r"(b[0]), "r"(b[1]));
}

// smem strides (bf16 elements); 144-byte rows -> conflict-free frag loads
#define ASTRIDE 72
#define A_BYTES (128 * ASTRIDE * 2)     // 18432
#define B_BYTES (64  * ASTRIDE * 2)     // 9216
#define HM_SMEM (2 * (A_BYTES + B_BYTES))  // 55296

// ---------------------------------------------------------------------------
// split helper: fp32 -> (bf16 hi, bf16 lo) x4
// ---------------------------------------------------------------------------
__device__ __forceinline__ void split4(const float* v,
                                       __nv_bfloat16* hp, __nv_bfloat16* lp) {
#pragma unroll
    for (int j = 0; j < 4; j += 2) {
        __nv_bfloat16 h0 = __float2bfloat16(v[j]);
        __nv_bfloat16 h1 = __float2bfloat16(v[j + 1]);
        __nv_bfloat16 l0 = __float2bfloat16(v[j]     - __bfloat162float(h0));
        __nv_bfloat16 l1 = __float2bfloat16(v[j + 1] - __bfloat162float(h1));
        __nv_bfloat162 hh; hh.x = h0; hh.y = h1;
        __nv_bfloat162 ll; ll.x = l0; ll.y = l1;
        *(__nv_bfloat162*)(hp + j) = hh;
        *(__nv_bfloat162*)(lp + j) = ll;
    }
}

// ---------------------------------------------------------------------------
// split x (fp32 [4096,512]) into hi/lo bf16
// ---------------------------------------------------------------------------
__global__ __launch_bounds__(NT)
void splitx_kernel(const float* __restrict__ x,
                   __nv_bfloat16* __restrict__ xh,
                   __nv_bfloat16* __restrict__ xl)
{
    const size_t i4 = (size_t)blockIdx.x * NT + threadIdx.x;
    float4 v = ((const float4*)x)[i4];
    float vv[4] = {v.x, v.y, v.z, v.w};
    split4(vv, xh + i4 * 4, xl + i4 * 4);
}

// ---------------------------------------------------------------------------
// transpose + split 7 weights [512,512]: W[k][n] -> Wt_hi/lo[n][k] bf16
// ---------------------------------------------------------------------------
struct WPack { const float* w[7]; };

__global__ __launch_bounds__(NT)
void splitw_kernel(WPack p, __nv_bfloat16* __restrict__ base)
{
    const int wi = blockIdx.z;
    const float* W = p.w[wi];
    __nv_bfloat16* hO = base + (size_t)wi * 524288;
    __nv_bfloat16* lO = hO + 262144;
    __shared__ float t[32][33];
    const int n0 = blockIdx.x * 32, k0 = blockIdx.y * 32;
    const int lane = threadIdx.x & 31, ty = threadIdx.x >> 5;
#pragma unroll
    for (int p2 = 0; p2 < 4; ++p2) {
        int r = p2 * 8 + ty;
        t[r][lane] = W[(size_t)(k0 + r) * 512 + n0 + lane];
    }
    __syncthreads();
#pragma unroll
    for (int p2 = 0; p2 < 4; ++p2) {
        int r = p2 * 8 + ty;                 // n offset
        float v = t[lane][r];                // = W[k0+lane][n0+r]
        __nv_bfloat16 h = __float2bfloat16(v);
        __nv_bfloat16 l = __float2bfloat16(v - __bfloat162float(h));
        size_t o = (size_t)(n0 + r) * 512 + k0 + lane;
        hO[o] = h;
        lO[o] = l;
    }
}

// ---------------------------------------------------------------------------
// HMMA GEMM: C[4096,512] = (Ah+Al) @ (Bh+Bl)^T + bias  (B stored [N,K])
// CTA 128(M) x 64(N); 8 warps 4(M)x2(N); warp tile 32x32 (2x4 m16n8k16).
// K-loop: 24 chunks of 64 (3 split phases x 8).
// ---------------------------------------------------------------------------
__global__ __launch_bounds__(NT)
void hmma_gemm_kernel(const __nv_bfloat16* __restrict__ Ah,
                      const __nv_bfloat16* __restrict__ Al,
                      const __nv_bfloat16* __restrict__ Bh,
                      const __nv_bfloat16* __restrict__ Bl,
                      const float* __restrict__ bias,
                      float* __restrict__ C)
{
    extern __shared__ __align__(16) __nv_bfloat16 smem[];
    __nv_bfloat16* Abuf[2] = {smem, smem + (A_BYTES + B_BYTES) / 2};
    __nv_bfloat16* Bbuf[2] = {smem + A_BYTES / 2,
                              smem + (2 * A_BYTES + B_BYTES) / 2};

    const int tid  = threadIdx.x;
    const int wid  = tid >> 5;
    const int lid  = tid & 31;
    const int m0   = blockIdx.y * 128;
    const int n0   = blockIdx.x * 64;
    const int wm   = (wid & 3) * 32;
    const int wn   = (wid >> 2) * 32;
    const int g    = lid >> 2;          // group id 0..7
    const int tg   = (lid & 3) * 2;     // element pair 0,2,4,6

    // loaders
    const int arow = tid >> 1;             // 0..127
    const int ahof = (tid & 1) * 32;       // bf16 offset within 64-elem row
    const int brow = tid >> 2;             // 0..63
    const int bqof = (tid & 3) * 16;

    uint4 aR[4], bR[2];

    auto load_chunk = [&](int c) {
        const int phase = c >> 3;
        const int kc = (c & 7) << 6;
        const __nv_bfloat16* As = (phase == 1) ? Al : Ah;
        const __nv_bfloat16* Bs = (phase == 2) ? Bl : Bh;
        const uint4* ap = (const uint4*)(As + (size_t)(m0 + arow) * 512 + kc + ahof);
#pragma unroll
        for (int i = 0; i < 4; ++i) aR[i] = ap[i];
        const uint4* bp = (const uint4*)(Bs + (size_t)(n0 + brow) * 512 + kc + bqof);
#pragma unroll
        for (int i = 0; i < 2; ++i) bR[i] = bp[i];
    };
    auto store_chunk = [&](int buf) {
        uint4* ad = (uint4*)(Abuf[buf] + arow * ASTRIDE + ahof);
#pragma unroll
        for (int i = 0; i < 4; ++i) ad[i] = aR[i];
        uint4* bd = (uint4*)(Bbuf[buf] + brow * ASTRIDE + bqof);
#pragma unroll
        for (int i = 0; i < 2; ++i) bd[i] = bR[i];
    };

    float acc[2][4][4] = {};

    auto compute = [&](int buf) {
        const __nv_bfloat16* As = Abuf[buf];
        const __nv_bfloat16* Bs = Bbuf[buf];
#pragma unroll
        for (int k16 = 0; k16 < 4; ++k16) {
            const int kc = k16 * 16;
            uint32_t af[2][4];
#pragma unroll
            for (int mi = 0; mi < 2; ++mi) {
                const __nv_bfloat16* base =
                    As + (wm + mi * 16 + g) * ASTRIDE + kc + tg;
                af[mi][0] = *(const uint32_t*)(base);
                af[mi][1] = *(const uint32_t*)(base + 8 * ASTRIDE);
                af[mi][2] = *(const uint32_t*)(base + 8);
                af[mi][3] = *(const uint32_t*)(base + 8 * ASTRIDE + 8);
            }
            uint32_t bfr[4][2];
#pragma unroll
            for (int ni = 0; ni < 4; ++ni) {
                const __nv_bfloat16* base =
                    Bs + (wn + ni * 8 + g) * ASTRIDE + kc + tg;
                bfr[ni][0] = *(const uint32_t*)(base);
                bfr[ni][1] = *(const uint32_t*)(base + 8);
            }
#pragma unroll
            for (int mi = 0; mi < 2; ++mi)
#pragma unroll
                for (int ni = 0; ni < 4; ++ni)
                    mma16816(acc[mi][ni], af[mi], bfr[ni]);
        }
    };

    load_chunk(0);
    store_chunk(0);
    __syncthreads();

    for (int c = 0; c < 24; ++c) {
        const int cur = c & 1;
        const bool more = (c + 1) < 24;
        if (more) load_chunk(c + 1);
        compute(cur);
        if (more) store_chunk(cur ^ 1);
        __syncthreads();
    }

    // epilogue
#pragma unroll
    for (int mi = 0; mi < 2; ++mi) {
        const int r0 = m0 + wm + mi * 16 + g;
#pragma unroll
        for (int ni = 0; ni < 4; ++ni) {
            const int col = n0 + wn + ni * 8 + tg;
            const float b0 = bias[col], b1 = bias[col + 1];
            float2 lo = {acc[mi][ni][0] + b0, acc[mi][ni][1] + b1};
            float2 hi = {acc[mi][ni][2] + b0, acc[mi][ni][3] + b1};
            *(float2*)&C[(size_t)r0 * 512 + col]       = lo;
            *(float2*)&C[(size_t)(r0 + 8) * 512 + col] = hi;
        }
    }
}

// ---------------------------------------------------------------------------
// scores: per (b,h):  C[i][j] = 0.125 * sum_d q[i,d] k[j,d]   (128x64, K=64)
// ---------------------------------------------------------------------------
__global__ __launch_bounds__(NT)
void scores_kernel(const float* __restrict__ qg,
                   const float* __restrict__ kg,
                   float* __restrict__ At)
{
    const int bh = blockIdx.z;
    const int b  = bh >> 3, h = bh & 7;
    const float* A  = qg + (size_t)b * 524288 + h * 64;
    const float* Bm = kg + (size_t)b * 524288 + h * 64;
    float* C = At + (size_t)bh * 1048576;

    __shared__ float As[16][128];
    __shared__ float Bs[16][64];

    const int tid = threadIdx.x;
    const int m0  = blockIdx.y * 128;
    const int n0  = blockIdx.x * 64;
    const int ar  = tid >> 1;
    const int ac  = (tid & 1) * 8;
    const int br  = tid >> 2;
    const int bq2 = (tid & 3) * 4;
    const int tx  = tid & 15;
    const int ty  = tid >> 4;

    const float* Ap = A  + (size_t)(m0 + ar) * 512 + ac;
    const float* Bp = Bm + (size_t)(n0 + br) * 512 + bq2;

    float4 a0 = *(const float4*)(Ap);
    float4 a1 = *(const float4*)(Ap + 4);
    float4 b0 = *(const float4*)(Bp);

    float acc[8][4] = {};

    for (int k0 = 0; k0 < 64; k0 += 16) {
        As[ac + 0][ar] = a0.x; As[ac + 1][ar] = a0.y;
        As[ac + 2][ar] = a0.z; As[ac + 3][ar] = a0.w;
        As[ac + 4][ar] = a1.x; As[ac + 5][ar] = a1.y;
        As[ac + 6][ar] = a1.z; As[ac + 7][ar] = a1.w;
        Bs[bq2 + 0][br] = b0.x; Bs[bq2 + 1][br] = b0.y;
        Bs[bq2 + 2][br] = b0.z; Bs[bq2 + 3][br] = b0.w;
        __syncthreads();
        if (k0 + 16 < 64) {
            a0 = *(const float4*)(Ap + k0 + 16);
            a1 = *(const float4*)(Ap + k0 + 20);
            b0 = *(const float4*)(Bp + k0 + 16);
        }
#pragma unroll
        for (int k = 0; k < 16; ++k) {
            float4 x0 = *(const float4*)&As[k][ty * 8];
            float4 x1 = *(const float4*)&As[k][ty * 8 + 4];
            float4 y  = *(const float4*)&Bs[k][tx * 4];
            float xa[8] = {x0.x, x0.y, x0.z, x0.w, x1.x, x1.y, x1.z, x1.w};
            float yb[4] = {y.x, y.y, y.z, y.w};
#pragma unroll
            for (int i = 0; i < 8; ++i)
#pragma unroll
                for (int j = 0; j < 4; ++j)
                    acc[i][j] = fmaf(xa[i], yb[j], acc[i][j]);
        }
        __syncthreads();
    }

#pragma unroll
    for (int i = 0; i < 8; ++i) {
        float4 r;
        r.x = acc[i][0] * 0.125f; r.y = acc[i][1] * 0.125f;
        r.z = acc[i][2] * 0.125f; r.w = acc[i][3] * 0.125f;
        *(float4*)&C[(size_t)(m0 + ty * 8 + i) * 1024 + n0 + tx * 4] = r;
    }
}

// ---------------------------------------------------------------------------
// fused softmax / z / masks / masked-softmax stats
// ---------------------------------------------------------------------------
__device__ __forceinline__ float warpMaxF(float v) {
#pragma unroll
    for (int o = 16; o; o >>= 1) v = fmaxf(v, __shfl_xor_sync(0xffffffffu, v, o));
    return v;
}
__device__ __forceinline__ float warpSumF(float v) {
#pragma unroll
    for (int o = 16; o; o >>= 1) v += __shfl_xor_sync(0xffffffffu, v, o);
    return v;
}

__global__ __launch_bounds__(NT)
void fused_sm_kernel(float* __restrict__ At,
                     const float* __restrict__ cw,
                     const float* __restrict__ cbp,
                     unsigned char* __restrict__ maskbuf,
                     float* __restrict__ stats)
{
    const int bq = blockIdx.x;
    const int b  = bq >> 10;
    const int q  = bq & 1023;
    const int tid  = threadIdx.x;
    const int lane = tid & 31, wid = tid >> 5;

    __shared__ float red[16][8];
    __shared__ float fin[16];

    const float cb = cbp[0];
    const size_t rowbase = ((size_t)q << 10) + (size_t)tid * 4;

    float a[8][4];
    float lm[8];
#pragma unroll
    for (int h = 0; h < 8; ++h) {
        float4 v = *(const float4*)(At + (size_t)(b * 8 + h) * 1048576 + rowbase);
        a[h][0] = v.x; a[h][1] = v.y; a[h][2] = v.z; a[h][3] = v.w;
        lm[h] = fmaxf(fmaxf(v.x, v.y), fmaxf(v.z, v.w));
    }
#pragma unroll
    for (int h = 0; h < 8; ++h) {
        float w = warpMaxF(lm[h]);
        if (lane == 0) red[h][wid] = w;
    }
    __syncthreads();
    if (tid < 8) {
        float m = red[tid][0];
#pragma unroll
        for (int i = 1; i < 8; ++i) m = fmaxf(m, red[tid][i]);
        fin[tid] = m;
    }
    __syncthreads();
    float ls[8];
#pragma unroll
    for (int h = 0; h < 8; ++h) {
        float m = fin[h];
        float s = 0.f;
#pragma unroll
        for (int j = 0; j < 4; ++j) {
            a[h][j] = __expf(a[h][j] - m);
            s += a[h][j];
        }
        ls[h] = s;
    }
    __syncthreads();
#pragma unroll
    for (int h = 0; h < 8; ++h) {
        float w = warpSumF(ls[h]);
        if (lane == 0) red[h][wid] = w;
    }
    __syncthreads();
    if (tid < 8) {
        float s = red[tid][0];
#pragma unroll
        for (int i = 1; i < 8; ++i) s += red[tid][i];
        fin[tid] = 1.0f / s;
    }
    __syncthreads();

    float zacc[4] = {cb, cb, cb, cb};
#pragma unroll
    for (int h = 0; h < 8; ++h) {
        float inv = fin[h];
        float w   = cw[h];
#pragma unroll
        for (int j = 0; j < 4; ++j) {
            a[h][j] *= inv;
            zacc[j] = fmaf(a[h][j], w, zacc[j]);
        }
    }
    unsigned mby[4];
#pragma unroll
    for (int j = 0; j < 4; ++j) {
        unsigned mf = (zacc[j] <= 0.f) ? 1u : 0u;
        unsigned mr = (zacc[j] >= 0.f) ? 2u : 0u;
        mby[j] = mf | mr;
    }

    float lsf[8], lsr[8];
#pragma unroll
    for (int h = 0; h < 8; ++h) {
        float sf = 0.f, sr = 0.f;
#pragma unroll
        for (int j = 0; j < 4; ++j) {
            float t = __expf(a[h][j]);
            a[h][j] = t;
            sf += (mby[j] & 1u) ? t : 1.0f;
            sr += (mby[j] & 2u) ? t : 1.0f;
        }
        lsf[h] = sf; lsr[h] = sr;
    }
    __syncthreads();
#pragma unroll
    for (int h = 0; h < 8; ++h) {
        float w = warpSumF(lsf[h]);
        if (lane == 0) red[h][wid] = w;
        w = warpSumF(lsr[h]);
        if (lane == 0) red[8 + h][wid] = w;
    }
    __syncthreads();
    if (tid < 16) {
        float s = red[tid][0];
#pragma unroll
        for (int i = 1; i < 8; ++i) s += red[tid][i];
        float inv = 1.0f / s;
        int h = tid & 7;
        int row = (b * 8 + h) * 1024 + q;
        if (tid < 8) stats[row] = inv;
        else         stats[32768 + row] = inv;
    }

#pragma unroll
    for (int h = 0; h < 8; ++h) {
        float4 v = {a[h][0], a[h][1], a[h][2], a[h][3]};
        *(float4*)(At + (size_t)(b * 8 + h) * 1048576 + rowbase) = v;
    }
    uchar4 m4 = {(unsigned char)mby[0], (unsigned char)mby[1],
                 (unsigned char)mby[2], (unsigned char)mby[3]};
    *(uchar4*)(maskbuf + (size_t)bq * 1024 + tid * 4) = m4;
}

// ---------------------------------------------------------------------------
// av: Tf = [(mf? t:1) @ v]*rsf, Tr likewise; epilogue emits bf16 hi/lo splits
// ---------------------------------------------------------------------------
__global__ __launch_bounds__(NT)
void av_kernel(const float* __restrict__ At,
               const unsigned char* __restrict__ maskb,
               const float* __restrict__ stats,
               const float* __restrict__ vg,
               __nv_bfloat16* __restrict__ Tfh, __nv_bfloat16* __restrict__ Tfl,
               __nv_bfloat16* __restrict__ Trh, __nv_bfloat16* __restrict__ Trl)
{
    const int bh = blockIdx.y;
    const int b  = bh >> 3, h = bh & 7;
    const int q0 = blockIdx.x * 128;

    __shared__ float Af[16][128];
    __shared__ float Ar[16][128];
    __shared__ float Vs[16][64];
    __shared__ float ssf[128], ssr[128];

    const int tid = threadIdx.x;
    if (tid < 128) {
        ssf[tid] = stats[bh * 1024 + q0 + tid];
        ssr[tid] = stats[32768 + bh * 1024 + q0 + tid];
    }

    const int ar = tid >> 1;
    const int ac = (tid & 1) * 8;
    const int vr = tid >> 4;
    const int vc = (tid & 15) * 4;
    const int tx = tid & 15;
    const int ty = tid >> 4;

    const float* tp = At + (size_t)bh * 1048576 + (size_t)(q0 + ar) * 1024 + ac;
    const unsigned char* mp = maskb + (((size_t)b << 10) + q0 + ar) * 1024 + ac;
    const float* vp = vg + (((size_t)b << 10) + vr) * 512 + h * 64 + vc;

    float4 t0 = *(const float4*)(tp);
    float4 t1 = *(const float4*)(tp + 4);
    uint2  mk = *(const uint2*)(mp);
    float4 v4 = *(const float4*)(vp);

    float accf[8][4] = {};
    float accr[8][4] = {};

    for (int k0 = 0; k0 < 1024; k0 += 16) {
        float tv[8] = {t0.x, t0.y, t0.z, t0.w, t1.x, t1.y, t1.z, t1.w};
        unsigned mb[8];
#pragma unroll
        for (int j = 0; j < 4; ++j) {
            mb[j]     = (mk.x >> (8 * j)) & 3u;
            mb[4 + j] = (mk.y >> (8 * j)) & 3u;
        }
#pragma unroll
        for (int j = 0; j < 8; ++j) {
            Af[ac + j][ar] = (mb[j] & 1u) ? tv[j] : 1.0f;
            Ar[ac + j][ar] = (mb[j] & 2u) ? tv[j] : 1.0f;
        }
        *(float4*)&Vs[vr][vc] = v4;
        __syncthreads();
        if (k0 + 16 < 1024) {
            t0 = *(const float4*)(tp + k0 + 16);
            t1 = *(const float4*)(tp + k0 + 20);
            mk = *(const uint2*)(mp + k0 + 16);
            v4 = *(const float4*)(vp + (size_t)(k0 + 16) * 512);
        }
#pragma unroll
        for (int k = 0; k < 16; ++k) {
            float4 f0 = *(const float4*)&Af[k][ty * 8];
            float4 f1 = *(const float4*)&Af[k][ty * 8 + 4];
            float4 r0 = *(const float4*)&Ar[k][ty * 8];
            float4 r1 = *(const float4*)&Ar[k][ty * 8 + 4];
            float4 vb = *(const float4*)&Vs[k][tx * 4];
            float fa[8] = {f0.x, f0.y, f0.z, f0.w, f1.x, f1.y, f1.z, f1.w};
            float ra[8] = {r0.x, r0.y, r0.z, r0.w, r1.x, r1.y, r1.z, r1.w};
            float vv[4] = {vb.x, vb.y, vb.z, vb.w};
#pragma unroll
            for (int i = 0; i < 8; ++i)
#pragma unroll
                for (int j = 0; j < 4; ++j) {
                    accf[i][j] = fmaf(fa[i], vv[j], accf[i][j]);
                    accr[i][j] = fmaf(ra[i], vv[j], accr[i][j]);
                }
        }
        __syncthreads();
    }

#pragma unroll
    for (int i = 0; i < 8; ++i) {
        float rf = ssf[ty * 8 + i];
        float rr = ssr[ty * 8 + i];
        size_t o = (((size_t)b << 10) + q0 + ty * 8 + i) * 512 + h * 64 + tx * 4;
        float fv[4] = {accf[i][0] * rf, accf[i][1] * rf, accf[i][2] * rf, accf[i][3] * rf};
        float rv[4] = {accr[i][0] * rr, accr[i][1] * rr, accr[i][2] * rr, accr[i][3] * rr};
        split4(fv, Tfh + o, Tfl + o);
        split4(rv, Trh + o, Trl + o);
    }
}

// ---------------------------------------------------------------------------
// out = F_f * w + F_r * (1-w),  w = sigmoid(sigmoid(G_f) - sigmoid(G_r))
// ---------------------------------------------------------------------------
__global__ __launch_bounds__(NT)
void combine_kernel(const float* __restrict__ Ff, const float* __restrict__ Gf,
                    const float* __restrict__ Fr, const float* __restrict__ Gr,
                    float* __restrict__ out)
{
    const size_t i4 = (size_t)blockIdx.x * NT + threadIdx.x;
    float4 ff = ((const float4*)Ff)[i4];
    float4 gf = ((const float4*)Gf)[i4];
    float4 fr = ((const float4*)Fr)[i4];
    float4 gr = ((const float4*)Gr)[i4];

    float ffv[4] = {ff.x, ff.y, ff.z, ff.w};
    float gfv[4] = {gf.x, gf.y, gf.z, gf.w};
    float frv[4] = {fr.x, fr.y, fr.z, fr.w};
    float grv[4] = {gr.x, gr.y, gr.z, gr.w};
    float ov[4];
#pragma unroll
    for (int j = 0; j < 4; ++j) {
        float sgf = 1.0f / (1.0f + __expf(-gfv[j]));
        float sgr = 1.0f / (1.0f + __expf(-grv[j]));
        float w   = 1.0f / (1.0f + __expf(sgr - sgf));
        ov[j] = ffv[j] * w + frv[j] * (1.0f - w);
    }
    float4 o = {ov[0], ov[1], ov[2], ov[3]};
    ((float4*)out)[i4] = o;
}

// ---------------------------------------------------------------------------
extern "C" void kernel_launch(void* const* d_in, const int* in_sizes, int n_in,
                              void* d_out, int out_size)
{
    const float* x   = (const float*)d_in[0];
    const float* Wq  = (const float*)d_in[1];
    const float* bq  = (const float*)d_in[2];
    const float* Wk  = (const float*)d_in[3];
    const float* bk  = (const float*)d_in[4];
    const float* Wv  = (const float*)d_in[5];
    const float* bv  = (const float*)d_in[6];
    const float* cw  = (const float*)d_in[7];
    const float* cb  = (const float*)d_in[8];
    const float* Wfh = (const float*)d_in[9];
    const float* bfh = (const float*)d_in[10];
    const float* Wfg = (const float*)d_in[11];
    const float* bfg = (const float*)d_in[12];
    const float* Wrh = (const float*)d_in[13];
    const float* brh = (const float*)d_in[14];
    const float* Wrg = (const float*)d_in[15];
    const float* brg = (const float*)d_in[16];
    float* out = (float*)d_out;

    float* s = nullptr;
    cudaGetSymbolAddress((void**)&s, g_scratch);
    __nv_bfloat16* bb = nullptr;
    cudaGetSymbolAddress((void**)&bb, g_bfbuf);

    float* q     = s + OFF_Q;
    float* k     = s + OFF_K;
    float* v     = s + OFF_V;
    float* Ff    = s + OFF_FF;
    float* Gf    = s + OFF_GF;
    float* Fr    = s + OFF_FR;
    float* Gr    = s + OFF_GR;
    unsigned char* maskb = (unsigned char*)(s + OFF_MB);
    float* stats = s + OFF_ST;
    float* At    = s + OFF_AT;

    __nv_bfloat16* xh  = bb + BX_H;
    __nv_bfloat16* xl  = bb + BX_L;
    __nv_bfloat16* tfh = bb + BTF_H;
    __nv_bfloat16* tfl = bb + BTF_L;
    __nv_bfloat16* trh = bb + BTR_H;
    __nv_bfloat16* trl = bb + BTR_L;
    __nv_bfloat16* wb  = bb + BW;

    cudaFuncSetAttribute(hmma_gemm_kernel,
                         cudaFuncAttributeMaxDynamicSharedMemorySize, HM_SMEM);

    // weight transpose+split (order: Wq, Wk, Wv, Wfh, Wfg, Wrh, Wrg)
    WPack wp;
    wp.w[0] = Wq;  wp.w[1] = Wk;  wp.w[2] = Wv;
    wp.w[3] = Wfh; wp.w[4] = Wfg; wp.w[5] = Wrh; wp.w[6] = Wrg;
    splitw_kernel<<<dim3(16, 16, 7), NT>>>(wp, wb);
    splitx_kernel<<<2048, NT>>>(x, xh, xl);

    dim3 gTC(8, 32);   // N/64, M/128

    hmma_gemm_kernel<<<gTC, NT, HM_SMEM>>>(xh, xl, wb + 0 * 524288, wb + 0 * 524288 + 262144, bq, q);
    hmma_gemm_kernel<<<gTC, NT, HM_SMEM>>>(xh, xl, wb + 1 * 524288, wb + 1 * 524288 + 262144, bk, k);
    hmma_gemm_kernel<<<gTC, NT, HM_SMEM>>>(xh, xl, wb + 2 * 524288, wb + 2 * 524288 + 262144, bv, v);

    scores_kernel<<<dim3(16, 8, 32), NT>>>(q, k, At);
    fused_sm_kernel<<<4096, NT>>>(At, cw, cb, maskb, stats);
    av_kernel<<<dim3(8, 32), NT>>>(At, maskb, stats, v, tfh, tfl, trh, trl);

    hmma_gemm_kernel<<<gTC, NT, HM_SMEM>>>(tfh, tfl, wb + 3 * 524288, wb + 3 * 524288 + 262144, bfh, Ff);
    hmma_gemm_kernel<<<gTC, NT, HM_SMEM>>>(tfh, tfl, wb + 4 * 524288, wb + 4 * 524288 + 262144, bfg, Gf);
    hmma_gemm_kernel<<<gTC, NT, HM_SMEM>>>(trh, trl, wb + 5 * 524288, wb + 5 * 524288 + 262144, brh, Fr);
    hmma_gemm_kernel<<<gTC, NT, HM_SMEM>>>(trh, trl, wb + 6 * 524288, wb + 6 * 524288 + 262144, brg, Gr);

    combine_kernel<<<2048, NT>>>(Ff, Gf, Fr, Gr, out);
}

// round 7
// speedup vs baseline: 1.7706x; 1.2071x over previous
#include <cuda_runtime.h>
#include <cuda_bf16.h>
#include <cstdint>

// ---------------------------------------------------------------------------
// ComplementaryAttention  B=4 T=1024 D=512 H=8 hd=64   (round 6)
//   - hmma_gemm v2: ldmatrix.x4 fragments + cp.async double-buffered pipeline
//   - scores on HMMA (bf16 split q/k produced directly by qkv gemm epilogue)
// ---------------------------------------------------------------------------

#define NT 256

// fp32 scratch (floats)
#define OFF_V   (4ull  * 1024 * 1024)
#define OFF_FF  (10ull * 1024 * 1024)
#define OFF_GF  (12ull * 1024 * 1024)
#define OFF_FR  (14ull * 1024 * 1024)
#define OFF_GR  (16ull * 1024 * 1024)
#define OFF_MB  (18ull * 1024 * 1024)
#define OFF_ST  (22ull * 1024 * 1024)
#define OFF_AT  (23ull * 1024 * 1024)

__device__ float g_scratch[56ull * 1024ull * 1024ull];

// bf16 scratch (elements)
#define BX_H   (0ull)
#define BX_L   (2ull  * 1024 * 1024)
#define BTF_H  (4ull  * 1024 * 1024)
#define BTF_L  (6ull  * 1024 * 1024)
#define BTR_H  (8ull  * 1024 * 1024)
#define BTR_L  (10ull * 1024 * 1024)
#define BW     (12ull * 1024 * 1024)   // 7 x (hi 256K + lo 256K) = 3.5M
#define BQ_H   (16ull * 1024 * 1024)
#define BQ_L   (18ull * 1024 * 1024)
#define BK_H   (20ull * 1024 * 1024)
#define BK_L   (22ull * 1024 * 1024)

__device__ __nv_bfloat16 g_bfbuf[24ull * 1024ull * 1024ull];

// ---------------------------------------------------------------------------
// PTX helpers
// ---------------------------------------------------------------------------
__device__ __forceinline__ void mma16816(float* c, const uint32_t* a,
                                         const uint32_t* b) {
    asm volatile(
        "mma.sync.aligned.m16n8k16.row.col.f32.bf16.bf16.f32 "
        "{%0,%1,%2,%3}, {%4,%5,%6,%7}, {%8,%9}, {%0,%1,%2,%3};"
        : "+f"(c[0]), "+f"(c[1]), "+f"(c[2]), "+f"(c[3])
        : "r"(a[0]), "r"(a[1]), "r"(a[2]), "r"(a[3]), "r"(b[0]), "r"(b[1]));
}

#define LDSM4(r, addr) \
    asm volatile("ldmatrix.sync.aligned.m8n8.x4.shared.b16 {%0,%1,%2,%3}, [%4];" \
        : "=r"((r)[0]), "=r"((r)[1]), "=r"((r)[2]), "=r"((r)[3]) : "r"(addr))

__device__ __forceinline__ void cpa16(uint32_t d, const void* s) {
    asm volatile("cp.async.cg.shared.global [%0], [%1], 16;" :: "r"(d), "l"(s));
}
#define CP_COMMIT() asm volatile("cp.async.commit_group;" ::: "memory")
#define CP_WAIT(n)  asm volatile("cp.async.wait_group %0;" :: "n"(n) : "memory")

// 144-byte padded rows: ldmatrix rows hit banks 4r mod 32 -> conflict-free
#define ASTRIDE 72
#define A_ELEMS (128 * ASTRIDE)
#define B_ELEMS (64  * ASTRIDE)
#define STAGE_ELEMS (A_ELEMS + B_ELEMS)
#define HM_SMEM (2 * STAGE_ELEMS * 2)           // 55296 bytes
#define SC_TILE (128 * ASTRIDE * 2)             // 18432 bytes
#define SC_SMEM (4 * SC_TILE)                   // 73728 bytes

// ---------------------------------------------------------------------------
// split helpers
// ---------------------------------------------------------------------------
__device__ __forceinline__ void split2w(float v0, float v1,
                                        __nv_bfloat16* hp, __nv_bfloat16* lp) {
    __nv_bfloat16 h0 = __float2bfloat16(v0);
    __nv_bfloat16 h1 = __float2bfloat16(v1);
    __nv_bfloat162 hh; hh.x = h0; hh.y = h1;
    __nv_bfloat162 ll;
    ll.x = __float2bfloat16(v0 - __bfloat162float(h0));
    ll.y = __float2bfloat16(v1 - __bfloat162float(h1));
    *(__nv_bfloat162*)hp = hh;
    *(__nv_bfloat162*)lp = ll;
}
__device__ __forceinline__ void split4(const float* v,
                                       __nv_bfloat16* hp, __nv_bfloat16* lp) {
    split2w(v[0], v[1], hp, lp);
    split2w(v[2], v[3], hp + 2, lp + 2);
}

// ---------------------------------------------------------------------------
// split x (fp32 [4096,512]) into hi/lo bf16
// ---------------------------------------------------------------------------
__global__ __launch_bounds__(NT)
void splitx_kernel(const float* __restrict__ x,
                   __nv_bfloat16* __restrict__ xh,
                   __nv_bfloat16* __restrict__ xl)
{
    const size_t i4 = (size_t)blockIdx.x * NT + threadIdx.x;
    float4 v = ((const float4*)x)[i4];
    float vv[4] = {v.x, v.y, v.z, v.w};
    split4(vv, xh + i4 * 4, xl + i4 * 4);
}

// ---------------------------------------------------------------------------
// transpose + split 7 weights [512,512]: W[k][n] -> Wt_hi/lo[n][k] bf16
// ---------------------------------------------------------------------------
struct WPack { const float* w[7]; };

__global__ __launch_bounds__(NT)
void splitw_kernel(WPack p, __nv_bfloat16* __restrict__ base)
{
    const int wi = blockIdx.z;
    const float* W = p.w[wi];
    __nv_bfloat16* hO = base + (size_t)wi * 524288;
    __nv_bfloat16* lO = hO + 262144;
    __shared__ float t[32][33];
    const int n0 = blockIdx.x * 32, k0 = blockIdx.y * 32;
    const int lane = threadIdx.x & 31, ty = threadIdx.x >> 5;
#pragma unroll
    for (int p2 = 0; p2 < 4; ++p2) {
        int r = p2 * 8 + ty;
        t[r][lane] = W[(size_t)(k0 + r) * 512 + n0 + lane];
    }
    __syncthreads();
#pragma unroll
    for (int p2 = 0; p2 < 4; ++p2) {
        int r = p2 * 8 + ty;
        float v = t[lane][r];
        __nv_bfloat16 h = __float2bfloat16(v);
        __nv_bfloat16 l = __float2bfloat16(v - __bfloat162float(h));
        size_t o = (size_t)(n0 + r) * 512 + k0 + lane;
        hO[o] = h;
        lO[o] = l;
    }
}

// ---------------------------------------------------------------------------
// HMMA GEMM v2: C[4096,512] = (Ah+Al)@(Bh+Bl)^T + bias
// ldmatrix fragments, cp.async 2-stage pipeline.
// mode 0: fp32 C.  mode 1: bf16 split (Ch, Cl).
// ---------------------------------------------------------------------------
__global__ __launch_bounds__(NT)
void hmma_gemm_kernel(const __nv_bfloat16* __restrict__ Ah,
                      const __nv_bfloat16* __restrict__ Al,
                      const __nv_bfloat16* __restrict__ Bh,
                      const __nv_bfloat16* __restrict__ Bl,
                      const float* __restrict__ bias,
                      float* __restrict__ C,
                      __nv_bfloat16* __restrict__ Ch,
                      __nv_bfloat16* __restrict__ Cl,
                      int mode)
{
    extern __shared__ __align__(16) __nv_bfloat16 smem[];
    const uint32_t smemU = (uint32_t)__cvta_generic_to_shared(smem);
    const int tid = threadIdx.x, lane = tid & 31, wid = tid >> 5;
    const int m0 = blockIdx.y * 128, n0 = blockIdx.x * 64;
    const int wm = (wid & 3) * 32, wn = (wid >> 2) * 32;
    const int arow = tid >> 1, ahof = (tid & 1) * 32;
    const int brow = tid >> 2, bqof = (tid & 3) * 16;

    auto load_chunk = [&](int c, int buf) {
        const int phase = c >> 3, kc = (c & 7) << 6;
        const __nv_bfloat16* As = (phase == 1) ? Al : Ah;
        const __nv_bfloat16* Bs = (phase == 2) ? Bl : Bh;
        const uint32_t ab = smemU + buf * (STAGE_ELEMS * 2);
        const uint32_t bb = ab + A_ELEMS * 2;
        const __nv_bfloat16* as = As + (size_t)(m0 + arow) * 512 + kc + ahof;
        const uint32_t ad = ab + (arow * ASTRIDE + ahof) * 2;
#pragma unroll
        for (int i = 0; i < 4; ++i) cpa16(ad + i * 16, as + i * 8);
        const __nv_bfloat16* bs = Bs + (size_t)(n0 + brow) * 512 + kc + bqof;
        const uint32_t bd = bb + (brow * ASTRIDE + bqof) * 2;
#pragma unroll
        for (int i = 0; i < 2; ++i) cpa16(bd + i * 16, bs + i * 8);
        CP_COMMIT();
    };

    float acc[2][4][4] = {};
    const uint32_t aFrag =
        ((wm + (lane & 7) + ((lane >> 3) & 1) * 8) * ASTRIDE +
         ((lane >> 4) & 1) * 8) * 2;
    const uint32_t bFrag =
        ((wn + (lane & 7) + ((lane >> 4) & 1) * 8) * ASTRIDE +
         ((lane >> 3) & 1) * 8) * 2;

    auto compute = [&](int buf) {
        const uint32_t ab = smemU + buf * (STAGE_ELEMS * 2);
        const uint32_t aA = ab + aFrag;
        const uint32_t bA = ab + A_ELEMS * 2 + bFrag;
#pragma unroll
        for (int k16 = 0; k16 < 4; ++k16) {
            const uint32_t ko = k16 * 32;
            uint32_t a0[4], a1[4], b0[4], b1[4];
            LDSM4(a0, aA + ko);
            LDSM4(a1, aA + 16 * ASTRIDE * 2 + ko);
            LDSM4(b0, bA + ko);
            LDSM4(b1, bA + 16 * ASTRIDE * 2 + ko);
            mma16816(acc[0][0], a0, b0);     mma16816(acc[0][1], a0, b0 + 2);
            mma16816(acc[0][2], a0, b1);     mma16816(acc[0][3], a0, b1 + 2);
            mma16816(acc[1][0], a1, b0);     mma16816(acc[1][1], a1, b0 + 2);
            mma16816(acc[1][2], a1, b1);     mma16816(acc[1][3], a1, b1 + 2);
        }
    };

    load_chunk(0, 0);
    for (int c = 0; c < 24; ++c) {
        if (c + 1 < 24) {
            load_chunk(c + 1, (c + 1) & 1);
            CP_WAIT(1);
        } else {
            CP_WAIT(0);
        }
        __syncthreads();
        compute(c & 1);
        __syncthreads();
    }

    const int g = lane >> 2, tg = (lane & 3) * 2;
#pragma unroll
    for (int mi = 0; mi < 2; ++mi) {
        const int r0 = m0 + wm + mi * 16 + g;
#pragma unroll
        for (int ni = 0; ni < 4; ++ni) {
            const int col = n0 + wn + ni * 8 + tg;
            const float b0v = bias[col], b1v = bias[col + 1];
            float v00 = acc[mi][ni][0] + b0v, v01 = acc[mi][ni][1] + b1v;
            float v10 = acc[mi][ni][2] + b0v, v11 = acc[mi][ni][3] + b1v;
            const size_t o0 = (size_t)r0 * 512 + col;
            const size_t o1 = (size_t)(r0 + 8) * 512 + col;
            if (mode == 0) {
                float2 lo = {v00, v01};
                float2 hi = {v10, v11};
                *(float2*)&C[o0] = lo;
                *(float2*)&C[o1] = hi;
            } else {
                split2w(v00, v01, Ch + o0, Cl + o0);
                split2w(v10, v11, Ch + o1, Cl + o1);
            }
        }
    }
}

// ---------------------------------------------------------------------------
// scores (HMMA): per (b,h): At = 0.125 * (qh+ql)(kh+kl)^T
// CTA 128x128, K=64 single shot, 3 split passes.
// ---------------------------------------------------------------------------
__global__ __launch_bounds__(NT)
void scores_hmma_kernel(const __nv_bfloat16* __restrict__ qh,
                        const __nv_bfloat16* __restrict__ ql,
                        const __nv_bfloat16* __restrict__ kh,
                        const __nv_bfloat16* __restrict__ kl,
                        float* __restrict__ At)
{
    extern __shared__ __align__(16) __nv_bfloat16 smem[];
    const uint32_t smemU = (uint32_t)__cvta_generic_to_shared(smem);
    const int bh = blockIdx.z, b = bh >> 3, h = bh & 7;
    const int m0 = blockIdx.y * 128, n0 = blockIdx.x * 128;
    const int tid = threadIdx.x, lane = tid & 31, wid = tid >> 5;
    const int wm = (wid & 3) * 32, wn = (wid >> 2) * 64;

    const int row = tid >> 1, off = (tid & 1) * 32;
    const size_t qsrc = (size_t)(b * 1024 + m0 + row) * 512 + h * 64 + off;
    const size_t ksrc = (size_t)(b * 1024 + n0 + row) * 512 + h * 64 + off;
    const uint32_t dst = (row * ASTRIDE + off) * 2;
#pragma unroll
    for (int i = 0; i < 4; ++i) {
        cpa16(smemU + 0 * SC_TILE + dst + i * 16, qh + qsrc + i * 8);
        cpa16(smemU + 1 * SC_TILE + dst + i * 16, ql + qsrc + i * 8);
        cpa16(smemU + 2 * SC_TILE + dst + i * 16, kh + ksrc + i * 8);
        cpa16(smemU + 3 * SC_TILE + dst + i * 16, kl + ksrc + i * 8);
    }
    CP_COMMIT();
    CP_WAIT(0);
    __syncthreads();

    float acc[2][8][4] = {};
    const uint32_t aFrag =
        ((wm + (lane & 7) + ((lane >> 3) & 1) * 8) * ASTRIDE +
         ((lane >> 4) & 1) * 8) * 2;
    const uint32_t bFrag =
        ((wn + (lane & 7) + ((lane >> 4) & 1) * 8) * ASTRIDE +
         ((lane >> 3) & 1) * 8) * 2;

    const uint32_t aoffs[3] = {0u, SC_TILE, 0u};              // qh, ql, qh
    const uint32_t boffs[3] = {2u * SC_TILE, 2u * SC_TILE, 3u * SC_TILE};
#pragma unroll
    for (int pass = 0; pass < 3; ++pass) {
        const uint32_t aA = smemU + aoffs[pass] + aFrag;
        const uint32_t bA = smemU + boffs[pass] + bFrag;
#pragma unroll
        for (int k16 = 0; k16 < 4; ++k16) {
            const uint32_t ko = k16 * 32;
            uint32_t a0[4], a1[4], bf[4][4];
            LDSM4(a0, aA + ko);
            LDSM4(a1, aA + 16 * ASTRIDE * 2 + ko);
#pragma unroll
            for (int p = 0; p < 4; ++p)
                LDSM4(bf[p], bA + p * 16 * ASTRIDE * 2 + ko);
#pragma unroll
            for (int p = 0; p < 4; ++p) {
                mma16816(acc[0][2 * p],     a0, bf[p]);
                mma16816(acc[0][2 * p + 1], a0, bf[p] + 2);
                mma16816(acc[1][2 * p],     a1, bf[p]);
                mma16816(acc[1][2 * p + 1], a1, bf[p] + 2);
            }
        }
    }

    float* Cp = At + ((size_t)bh << 20);
    const int g = lane >> 2, tg = (lane & 3) * 2;
#pragma unroll
    for (int mi = 0; mi < 2; ++mi) {
        const int r0 = m0 + wm + mi * 16 + g;
#pragma unroll
        for (int ni = 0; ni < 8; ++ni) {
            const int col = n0 + wn + ni * 8 + tg;
            float2 lo = {acc[mi][ni][0] * 0.125f, acc[mi][ni][1] * 0.125f};
            float2 hi = {acc[mi][ni][2] * 0.125f, acc[mi][ni][3] * 0.125f};
            *(float2*)&Cp[(size_t)r0 * 1024 + col] = lo;
            *(float2*)&Cp[(size_t)(r0 + 8) * 1024 + col] = hi;
        }
    }
}

// ---------------------------------------------------------------------------
// fused softmax / z / masks / masked-softmax stats
// ---------------------------------------------------------------------------
__device__ __forceinline__ float warpMaxF(float v) {
#pragma unroll
    for (int o = 16; o; o >>= 1) v = fmaxf(v, __shfl_xor_sync(0xffffffffu, v, o));
    return v;
}
__device__ __forceinline__ float warpSumF(float v) {
#pragma unroll
    for (int o = 16; o; o >>= 1) v += __shfl_xor_sync(0xffffffffu, v, o);
    return v;
}

__global__ __launch_bounds__(NT)
void fused_sm_kernel(float* __restrict__ At,
                     const float* __restrict__ cw,
                     const float* __restrict__ cbp,
                     unsigned char* __restrict__ maskbuf,
                     float* __restrict__ stats)
{
    const int bq = blockIdx.x;
    const int b  = bq >> 10;
    const int q  = bq & 1023;
    const int tid  = threadIdx.x;
    const int lane = tid & 31, wid = tid >> 5;

    __shared__ float red[16][8];
    __shared__ float fin[16];

    const float cb = cbp[0];
    const size_t rowbase = ((size_t)q << 10) + (size_t)tid * 4;

    float a[8][4];
    float lm[8];
#pragma unroll
    for (int h = 0; h < 8; ++h) {
        float4 v = *(const float4*)(At + (size_t)(b * 8 + h) * 1048576 + rowbase);
        a[h][0] = v.x; a[h][1] = v.y; a[h][2] = v.z; a[h][3] = v.w;
        lm[h] = fmaxf(fmaxf(v.x, v.y), fmaxf(v.z, v.w));
    }
#pragma unroll
    for (int h = 0; h < 8; ++h) {
        float w = warpMaxF(lm[h]);
        if (lane == 0) red[h][wid] = w;
    }
    __syncthreads();
    if (tid < 8) {
        float m = red[tid][0];
#pragma unroll
        for (int i = 1; i < 8; ++i) m = fmaxf(m, red[tid][i]);
        fin[tid] = m;
    }
    __syncthreads();
    float ls[8];
#pragma unroll
    for (int h = 0; h < 8; ++h) {
        float m = fin[h];
        float s = 0.f;
#pragma unroll
        for (int j = 0; j < 4; ++j) {
            a[h][j] = __expf(a[h][j] - m);
            s += a[h][j];
        }
        ls[h] = s;
    }
    __syncthreads();
#pragma unroll
    for (int h = 0; h < 8; ++h) {
        float w = warpSumF(ls[h]);
        if (lane == 0) red[h][wid] = w;
    }
    __syncthreads();
    if (tid < 8) {
        float s = red[tid][0];
#pragma unroll
        for (int i = 1; i < 8; ++i) s += red[tid][i];
        fin[tid] = 1.0f / s;
    }
    __syncthreads();

    float zacc[4] = {cb, cb, cb, cb};
#pragma unroll
    for (int h = 0; h < 8; ++h) {
        float inv = fin[h];
        float w   = cw[h];
#pragma unroll
        for (int j = 0; j < 4; ++j) {
            a[h][j] *= inv;
            zacc[j] = fmaf(a[h][j], w, zacc[j]);
        }
    }
    unsigned mby[4];
#pragma unroll
    for (int j = 0; j < 4; ++j) {
        unsigned mf = (zacc[j] <= 0.f) ? 1u : 0u;
        unsigned mr = (zacc[j] >= 0.f) ? 2u : 0u;
        mby[j] = mf | mr;
    }

    float lsf[8], lsr[8];
#pragma unroll
    for (int h = 0; h < 8; ++h) {
        float sf = 0.f, sr = 0.f;
#pragma unroll
        for (int j = 0; j < 4; ++j) {
            float t = __expf(a[h][j]);
            a[h][j] = t;
            sf += (mby[j] & 1u) ? t : 1.0f;
            sr += (mby[j] & 2u) ? t : 1.0f;
        }
        lsf[h] = sf; lsr[h] = sr;
    }
    __syncthreads();
#pragma unroll
    for (int h = 0; h < 8; ++h) {
        float w = warpSumF(lsf[h]);
        if (lane == 0) red[h][wid] = w;
        w = warpSumF(lsr[h]);
        if (lane == 0) red[8 + h][wid] = w;
    }
    __syncthreads();
    if (tid < 16) {
        float s = red[tid][0];
#pragma unroll
        for (int i = 1; i < 8; ++i) s += red[tid][i];
        float inv = 1.0f / s;
        int h = tid & 7;
        int row = (b * 8 + h) * 1024 + q;
        if (tid < 8) stats[row] = inv;
        else         stats[32768 + row] = inv;
    }

#pragma unroll
    for (int h = 0; h < 8; ++h) {
        float4 v = {a[h][0], a[h][1], a[h][2], a[h][3]};
        *(float4*)(At + (size_t)(b * 8 + h) * 1048576 + rowbase) = v;
    }
    uchar4 m4 = {(unsigned char)mby[0], (unsigned char)mby[1],
                 (unsigned char)mby[2], (unsigned char)mby[3]};
    *(uchar4*)(maskbuf + (size_t)bq * 1024 + tid * 4) = m4;
}

// ---------------------------------------------------------------------------
// av: Tf = [(mf? t:1) @ v]*rsf, Tr likewise; epilogue emits bf16 hi/lo splits
// ---------------------------------------------------------------------------
__global__ __launch_bounds__(NT)
void av_kernel(const float* __restrict__ At,
               const unsigned char* __restrict__ maskb,
               const float* __restrict__ stats,
               const float* __restrict__ vg,
               __nv_bfloat16* __restrict__ Tfh, __nv_bfloat16* __restrict__ Tfl,
               __nv_bfloat16* __restrict__ Trh, __nv_bfloat16* __restrict__ Trl)
{
    const int bh = blockIdx.y;
    const int b  = bh >> 3, h = bh & 7;
    const int q0 = blockIdx.x * 128;

    __shared__ float Af[16][128];
    __shared__ float Ar[16][128];
    __shared__ float Vs[16][64];
    __shared__ float ssf[128], ssr[128];

    const int tid = threadIdx.x;
    if (tid < 128) {
        ssf[tid] = stats[bh * 1024 + q0 + tid];
        ssr[tid] = stats[32768 + bh * 1024 + q0 + tid];
    }

    const int ar = tid >> 1;
    const int ac = (tid & 1) * 8;
    const int vr = tid >> 4;
    const int vc = (tid & 15) * 4;
    const int tx = tid & 15;
    const int ty = tid >> 4;

    const float* tp = At + (size_t)bh * 1048576 + (size_t)(q0 + ar) * 1024 + ac;
    const unsigned char* mp = maskb + (((size_t)b << 10) + q0 + ar) * 1024 + ac;
    const float* vp = vg + (((size_t)b << 10) + vr) * 512 + h * 64 + vc;

    float4 t0 = *(const float4*)(tp);
    float4 t1 = *(const float4*)(tp + 4);
    uint2  mk = *(const uint2*)(mp);
    float4 v4 = *(const float4*)(vp);

    float accf[8][4] = {};
    float accr[8][4] = {};

    for (int k0 = 0; k0 < 1024; k0 += 16) {
        float tv[8] = {t0.x, t0.y, t0.z, t0.w, t1.x, t1.y, t1.z, t1.w};
        unsigned mb[8];
#pragma unroll
        for (int j = 0; j < 4; ++j) {
            mb[j]     = (mk.x >> (8 * j)) & 3u;
            mb[4 + j] = (mk.y >> (8 * j)) & 3u;
        }
#pragma unroll
        for (int j = 0; j < 8; ++j) {
            Af[ac + j][ar] = (mb[j] & 1u) ? tv[j] : 1.0f;
            Ar[ac + j][ar] = (mb[j] & 2u) ? tv[j] : 1.0f;
        }
        *(float4*)&Vs[vr][vc] = v4;
        __syncthreads();
        if (k0 + 16 < 1024) {
            t0 = *(const float4*)(tp + k0 + 16);
            t1 = *(const float4*)(tp + k0 + 20);
            mk = *(const uint2*)(mp + k0 + 16);
            v4 = *(const float4*)(vp + (size_t)(k0 + 16) * 512);
        }
#pragma unroll
        for (int k = 0; k < 16; ++k) {
            float4 f0 = *(const float4*)&Af[k][ty * 8];
            float4 f1 = *(const float4*)&Af[k][ty * 8 + 4];
            float4 r0 = *(const float4*)&Ar[k][ty * 8];
            float4 r1 = *(const float4*)&Ar[k][ty * 8 + 4];
            float4 vb = *(const float4*)&Vs[k][tx * 4];
            float fa[8] = {f0.x, f0.y, f0.z, f0.w, f1.x, f1.y, f1.z, f1.w};
            float ra[8] = {r0.x, r0.y, r0.z, r0.w, r1.x, r1.y, r1.z, r1.w};
            float vv[4] = {vb.x, vb.y, vb.z, vb.w};
#pragma unroll
            for (int i = 0; i < 8; ++i)
#pragma unroll
                for (int j = 0; j < 4; ++j) {
                    accf[i][j] = fmaf(fa[i], vv[j], accf[i][j]);
                    accr[i][j] = fmaf(ra[i], vv[j], accr[i][j]);
                }
        }
        __syncthreads();
    }

#pragma unroll
    for (int i = 0; i < 8; ++i) {
        float rf = ssf[ty * 8 + i];
        float rr = ssr[ty * 8 + i];
        size_t o = (((size_t)b << 10) + q0 + ty * 8 + i) * 512 + h * 64 + tx * 4;
        float fv[4] = {accf[i][0] * rf, accf[i][1] * rf, accf[i][2] * rf, accf[i][3] * rf};
        float rv[4] = {accr[i][0] * rr, accr[i][1] * rr, accr[i][2] * rr, accr[i][3] * rr};
        split4(fv, Tfh + o, Tfl + o);
        split4(rv, Trh + o, Trl + o);
    }
}

// ---------------------------------------------------------------------------
// out = F_f * w + F_r * (1-w),  w = sigmoid(sigmoid(G_f) - sigmoid(G_r))
// ---------------------------------------------------------------------------
__global__ __launch_bounds__(NT)
void combine_kernel(const float* __restrict__ Ff, const float* __restrict__ Gf,
                    const float* __restrict__ Fr, const float* __restrict__ Gr,
                    float* __restrict__ out)
{
    const size_t i4 = (size_t)blockIdx.x * NT + threadIdx.x;
    float4 ff = ((const float4*)Ff)[i4];
    float4 gf = ((const float4*)Gf)[i4];
    float4 fr = ((const float4*)Fr)[i4];
    float4 gr = ((const float4*)Gr)[i4];

    float ffv[4] = {ff.x, ff.y, ff.z, ff.w};
    float gfv[4] = {gf.x, gf.y, gf.z, gf.w};
    float frv[4] = {fr.x, fr.y, fr.z, fr.w};
    float grv[4] = {gr.x, gr.y, gr.z, gr.w};
    float ov[4];
#pragma unroll
    for (int j = 0; j < 4; ++j) {
        float sgf = 1.0f / (1.0f + __expf(-gfv[j]));
        float sgr = 1.0f / (1.0f + __expf(-grv[j]));
        float w   = 1.0f / (1.0f + __expf(sgr - sgf));
        ov[j] = ffv[j] * w + frv[j] * (1.0f - w);
    }
    float4 o = {ov[0], ov[1], ov[2], ov[3]};
    ((float4*)out)[i4] = o;
}

// ---------------------------------------------------------------------------
extern "C" void kernel_launch(void* const* d_in, const int* in_sizes, int n_in,
                              void* d_out, int out_size)
{
    const float* x   = (const float*)d_in[0];
    const float* Wq  = (const float*)d_in[1];
    const float* bq  = (const float*)d_in[2];
    const float* Wk  = (const float*)d_in[3];
    const float* bk  = (const float*)d_in[4];
    const float* Wv  = (const float*)d_in[5];
    const float* bv  = (const float*)d_in[6];
    const float* cw  = (const float*)d_in[7];
    const float* cb  = (const float*)d_in[8];
    const float* Wfh = (const float*)d_in[9];
    const float* bfh = (const float*)d_in[10];
    const float* Wfg = (const float*)d_in[11];
    const float* bfg = (const float*)d_in[12];
    const float* Wrh = (const float*)d_in[13];
    const float* brh = (const float*)d_in[14];
    const float* Wrg = (const float*)d_in[15];
    const float* brg = (const float*)d_in[16];
    float* out = (float*)d_out;

    float* s = nullptr;
    cudaGetSymbolAddress((void**)&s, g_scratch);
    __nv_bfloat16* bb = nullptr;
    cudaGetSymbolAddress((void**)&bb, g_bfbuf);

    float* v     = s + OFF_V;
    float* Ff    = s + OFF_FF;
    float* Gf    = s + OFF_GF;
    float* Fr    = s + OFF_FR;
    float* Gr    = s + OFF_GR;
    unsigned char* maskb = (unsigned char*)(s + OFF_MB);
    float* stats = s + OFF_ST;
    float* At    = s + OFF_AT;

    __nv_bfloat16* xh  = bb + BX_H;
    __nv_bfloat16* xl  = bb + BX_L;
    __nv_bfloat16* tfh = bb + BTF_H;
    __nv_bfloat16* tfl = bb + BTF_L;
    __nv_bfloat16* trh = bb + BTR_H;
    __nv_bfloat16* trl = bb + BTR_L;
    __nv_bfloat16* wb  = bb + BW;
    __nv_bfloat16* qhb = bb + BQ_H;
    __nv_bfloat16* qlb = bb + BQ_L;
    __nv_bfloat16* khb = bb + BK_H;
    __nv_bfloat16* klb = bb + BK_L;

    cudaFuncSetAttribute(hmma_gemm_kernel,
                         cudaFuncAttributeMaxDynamicSharedMemorySize, HM_SMEM);
    cudaFuncSetAttribute(scores_hmma_kernel,
                         cudaFuncAttributeMaxDynamicSharedMemorySize, SC_SMEM);

    WPack wp;
    wp.w[0] = Wq;  wp.w[1] = Wk;  wp.w[2] = Wv;
    wp.w[3] = Wfh; wp.w[4] = Wfg; wp.w[5] = Wrh; wp.w[6] = Wrg;
    splitw_kernel<<<dim3(16, 16, 7), NT>>>(wp, wb);
    splitx_kernel<<<2048, NT>>>(x, xh, xl);

    dim3 gTC(8, 32);   // N/64, M/128

    hmma_gemm_kernel<<<gTC, NT, HM_SMEM>>>(xh, xl, wb + 0 * 524288, wb + 0 * 524288 + 262144, bq, nullptr, qhb, qlb, 1);
    hmma_gemm_kernel<<<gTC, NT, HM_SMEM>>>(xh, xl, wb + 1 * 524288, wb + 1 * 524288 + 262144, bk, nullptr, khb, klb, 1);
    hmma_gemm_kernel<<<gTC, NT, HM_SMEM>>>(xh, xl, wb + 2 * 524288, wb + 2 * 524288 + 262144, bv, v, nullptr, nullptr, 0);

    scores_hmma_kernel<<<dim3(8, 8, 32), NT, SC_SMEM>>>(qhb, qlb, khb, klb, At);
    fused_sm_kernel<<<4096, NT>>>(At, cw, cb, maskb, stats);
    av_kernel<<<dim3(8, 32), NT>>>(At, maskb, stats, v, tfh, tfl, trh, trl);

    hmma_gemm_kernel<<<gTC, NT, HM_SMEM>>>(tfh, tfl, wb + 3 * 524288, wb + 3 * 524288 + 262144, bfh, Ff, nullptr, nullptr, 0);
    hmma_gemm_kernel<<<gTC, NT, HM_SMEM>>>(tfh, tfl, wb + 4 * 524288, wb + 4 * 524288 + 262144, bfg, Gf, nullptr, nullptr, 0);
    hmma_gemm_kernel<<<gTC, NT, HM_SMEM>>>(trh, trl, wb + 5 * 524288, wb + 5 * 524288 + 262144, brh, Fr, nullptr, nullptr, 0);
    hmma_gemm_kernel<<<gTC, NT, HM_SMEM>>>(trh, trl, wb + 6 * 524288, wb + 6 * 524288 + 262144, brg, Gr, nullptr, nullptr, 0);

    combine_kernel<<<2048, NT>>>(Ff, Gf, Fr, Gr, out);
}

// round 8
// speedup vs baseline: 2.1933x; 1.2387x over previous
#include <cuda_runtime.h>
#include <cuda_bf16.h>
#include <cstdint>

// ---------------------------------------------------------------------------
// ComplementaryAttention  B=4 T=1024 D=512 H=8 hd=64   (round 8)
//   - av on HMMA via (t-1)/colsum decomposition (exact)
//   - merged qkv (z=3) and final (z=4) gemm launches
//   - frag-double-buffered hmma_gemm
// ---------------------------------------------------------------------------

#define NT 256

// fp32 scratch (floats)
#define OFF_FF  (10ull * 1024 * 1024)
#define OFF_GF  (12ull * 1024 * 1024)
#define OFF_FR  (14ull * 1024 * 1024)
#define OFF_GR  (16ull * 1024 * 1024)
#define OFF_MB  (18ull * 1024 * 1024)
#define OFF_ST  (22ull * 1024 * 1024)
#define OFF_CS  (22ull * 1024 * 1024 + 131072)
#define OFF_AT  (23ull * 1024 * 1024)

__device__ float g_scratch[56ull * 1024ull * 1024ull];

// bf16 scratch (elements)
#define BX_H   (0ull)
#define BX_L   (2ull  * 1024 * 1024)
#define BTF_H  (4ull  * 1024 * 1024)
#define BTF_L  (6ull  * 1024 * 1024)
#define BTR_H  (8ull  * 1024 * 1024)
#define BTR_L  (10ull * 1024 * 1024)
#define BW     (12ull * 1024 * 1024)
#define BQ_H   (16ull * 1024 * 1024)
#define BQ_L   (18ull * 1024 * 1024)
#define BK_H   (20ull * 1024 * 1024)
#define BK_L   (22ull * 1024 * 1024)
#define BV_H   (24ull * 1024 * 1024)
#define BV_L   (26ull * 1024 * 1024)
#define BT_H   (28ull * 1024 * 1024)   // (t-1) hi, 32M elems
#define BT_L   (60ull * 1024 * 1024)   // (t-1) lo, 32M elems

__device__ __nv_bfloat16 g_bfbuf[92ull * 1024ull * 1024ull];

// ---------------------------------------------------------------------------
// PTX helpers
// ---------------------------------------------------------------------------
__device__ __forceinline__ void mma16816(float* c, const uint32_t* a,
                                         const uint32_t* b) {
    asm volatile(
        "mma.sync.aligned.m16n8k16.row.col.f32.bf16.bf16.f32 "
        "{%0,%1,%2,%3}, {%4,%5,%6,%7}, {%8,%9}, {%0,%1,%2,%3};"
        : "+f"(c[0]), "+f"(c[1]), "+f"(c[2]), "+f"(c[3])
        : "r"(a[0]), "r"(a[1]), "r"(a[2]), "r"(a[3]), "r"(b[0]), "r"(b[1]));
}

#define LDSM4(r, addr) \
    asm volatile("ldmatrix.sync.aligned.m8n8.x4.shared.b16 {%0,%1,%2,%3}, [%4];" \
        : "=r"((r)[0]), "=r"((r)[1]), "=r"((r)[2]), "=r"((r)[3]) : "r"(addr))
#define LDSM4T(r, addr) \
    asm volatile("ldmatrix.sync.aligned.m8n8.x4.trans.shared.b16 {%0,%1,%2,%3}, [%4];" \
        : "=r"((r)[0]), "=r"((r)[1]), "=r"((r)[2]), "=r"((r)[3]) : "r"(addr))
#define STS128(addr, r0, r1, r2, r3) \
    asm volatile("st.shared.v4.b32 [%0], {%1,%2,%3,%4};" \
        :: "r"(addr), "r"(r0), "r"(r1), "r"(r2), "r"(r3))

__device__ __forceinline__ void cpa16(uint32_t d, const void* s) {
    asm volatile("cp.async.cg.shared.global [%0], [%1], 16;" :: "r"(d), "l"(s));
}
#define CP_COMMIT() asm volatile("cp.async.commit_group;" ::: "memory")
#define CP_WAIT(n)  asm volatile("cp.async.wait_group %0;" :: "n"(n) : "memory")

#define ASTRIDE 72
#define A_ELEMS (128 * ASTRIDE)
#define B_ELEMS (64  * ASTRIDE)
#define STAGE_ELEMS (A_ELEMS + B_ELEMS)
#define HM_SMEM (2 * STAGE_ELEMS * 2)
#define SC_TILE (128 * ASTRIDE * 2)
#define SC_SMEM (4 * SC_TILE)

// av smem tile offsets (elements within a stage)
#define AV_AFH 0
#define AV_AFL 4608
#define AV_ARH 9216
#define AV_ARL 13824
#define AV_VH  18432
#define AV_VL  23040
#define AV_STAGE 27648
#define AV_SMEM (2 * AV_STAGE * 2)   // 110592 bytes

// ---------------------------------------------------------------------------
__device__ __forceinline__ void split2w(float v0, float v1,
                                        __nv_bfloat16* hp, __nv_bfloat16* lp) {
    __nv_bfloat16 h0 = __float2bfloat16(v0);
    __nv_bfloat16 h1 = __float2bfloat16(v1);
    __nv_bfloat162 hh; hh.x = h0; hh.y = h1;
    __nv_bfloat162 ll;
    ll.x = __float2bfloat16(v0 - __bfloat162float(h0));
    ll.y = __float2bfloat16(v1 - __bfloat162float(h1));
    *(__nv_bfloat162*)hp = hh;
    *(__nv_bfloat162*)lp = ll;
}
__device__ __forceinline__ void split4(const float* v,
                                       __nv_bfloat16* hp, __nv_bfloat16* lp) {
    split2w(v[0], v[1], hp, lp);
    split2w(v[2], v[3], hp + 2, lp + 2);
}

// ---------------------------------------------------------------------------
__global__ __launch_bounds__(NT)
void splitx_kernel(const float* __restrict__ x,
                   __nv_bfloat16* __restrict__ xh,
                   __nv_bfloat16* __restrict__ xl)
{
    const size_t i4 = (size_t)blockIdx.x * NT + threadIdx.x;
    float4 v = ((const float4*)x)[i4];
    float vv[4] = {v.x, v.y, v.z, v.w};
    split4(vv, xh + i4 * 4, xl + i4 * 4);
}

struct WPack { const float* w[7]; };

__global__ __launch_bounds__(NT)
void splitw_kernel(WPack p, __nv_bfloat16* __restrict__ base)
{
    const int wi = blockIdx.z;
    const float* W = p.w[wi];
    __nv_bfloat16* hO = base + (size_t)wi * 524288;
    __nv_bfloat16* lO = hO + 262144;
    __shared__ float t[32][33];
    const int n0 = blockIdx.x * 32, k0 = blockIdx.y * 32;
    const int lane = threadIdx.x & 31, ty = threadIdx.x >> 5;
#pragma unroll
    for (int p2 = 0; p2 < 4; ++p2) {
        int r = p2 * 8 + ty;
        t[r][lane] = W[(size_t)(k0 + r) * 512 + n0 + lane];
    }
    __syncthreads();
#pragma unroll
    for (int p2 = 0; p2 < 4; ++p2) {
        int r = p2 * 8 + ty;
        float v = t[lane][r];
        __nv_bfloat16 h = __float2bfloat16(v);
        __nv_bfloat16 l = __float2bfloat16(v - __bfloat162float(h));
        size_t o = (size_t)(n0 + r) * 512 + k0 + lane;
        hO[o] = h;
        lO[o] = l;
    }
}

// ---------------------------------------------------------------------------
// HMMA GEMM, z-indexed job pack.
// ---------------------------------------------------------------------------
struct GJob {
    const __nv_bfloat16 *Ah, *Al, *Bh, *Bl;
    const float* bias;
    float* C;
    __nv_bfloat16 *Ch, *Cl;
    int mode;
};
struct GJobs { GJob j[4]; };

__global__ __launch_bounds__(NT)
void hmma_gemm_kernel(GJobs jobs)
{
    const GJob J = jobs.j[blockIdx.z];
    extern __shared__ __align__(16) __nv_bfloat16 smem[];
    const uint32_t smemU = (uint32_t)__cvta_generic_to_shared(smem);
    const int tid = threadIdx.x, lane = tid & 31, wid = tid >> 5;
    const int m0 = blockIdx.y * 128, n0 = blockIdx.x * 64;
    const int wm = (wid & 3) * 32, wn = (wid >> 2) * 32;
    const int arow = tid >> 1, ahof = (tid & 1) * 32;
    const int brow = tid >> 2, bqof = (tid & 3) * 16;

    auto load_chunk = [&](int c, int buf) {
        const int phase = c >> 3, kc = (c & 7) << 6;
        const __nv_bfloat16* As = (phase == 1) ? J.Al : J.Ah;
        const __nv_bfloat16* Bs = (phase == 2) ? J.Bl : J.Bh;
        const uint32_t ab = smemU + buf * (STAGE_ELEMS * 2);
        const uint32_t bb = ab + A_ELEMS * 2;
        const __nv_bfloat16* as = As + (size_t)(m0 + arow) * 512 + kc + ahof;
        const uint32_t ad = ab + (arow * ASTRIDE + ahof) * 2;
#pragma unroll
        for (int i = 0; i < 4; ++i) cpa16(ad + i * 16, as + i * 8);
        const __nv_bfloat16* bs = Bs + (size_t)(n0 + brow) * 512 + kc + bqof;
        const uint32_t bd = bb + (brow * ASTRIDE + bqof) * 2;
#pragma unroll
        for (int i = 0; i < 2; ++i) cpa16(bd + i * 16, bs + i * 8);
        CP_COMMIT();
    };

    float acc[2][4][4] = {};
    const uint32_t aFrag =
        ((wm + (lane & 15)) * ASTRIDE + ((lane >> 4) & 1) * 8) * 2;
    const uint32_t bFrag =
        ((wn + (lane & 7) + ((lane >> 4) & 1) * 8) * ASTRIDE +
         ((lane >> 3) & 1) * 8) * 2;

    auto compute = [&](int buf) {
        const uint32_t ab = smemU + buf * (STAGE_ELEMS * 2);
        const uint32_t aA = ab + aFrag;
        const uint32_t bA = ab + A_ELEMS * 2 + bFrag;
        uint32_t fr[2][16];
        auto ldf = [&](int k16, uint32_t* f) {
            const uint32_t ko = k16 * 32;
            LDSM4(f, aA + ko);
            LDSM4(f + 4, aA + 16 * ASTRIDE * 2 + ko);
            LDSM4(f + 8, bA + ko);
            LDSM4(f + 12, bA + 16 * ASTRIDE * 2 + ko);
        };
        ldf(0, fr[0]);
#pragma unroll
        for (int k16 = 0; k16 < 4; ++k16) {
            if (k16 < 3) ldf(k16 + 1, fr[(k16 + 1) & 1]);
            uint32_t* f = fr[k16 & 1];
            mma16816(acc[0][0], f, f + 8);      mma16816(acc[0][1], f, f + 10);
            mma16816(acc[0][2], f, f + 12);     mma16816(acc[0][3], f, f + 14);
            mma16816(acc[1][0], f + 4, f + 8);  mma16816(acc[1][1], f + 4, f + 10);
            mma16816(acc[1][2], f + 4, f + 12); mma16816(acc[1][3], f + 4, f + 14);
        }
    };

    load_chunk(0, 0);
    for (int c = 0; c < 24; ++c) {
        if (c + 1 < 24) {
            load_chunk(c + 1, (c + 1) & 1);
            CP_WAIT(1);
        } else {
            CP_WAIT(0);
        }
        __syncthreads();
        compute(c & 1);
        __syncthreads();
    }

    const int g = lane >> 2, tg = (lane & 3) * 2;
#pragma unroll
    for (int mi = 0; mi < 2; ++mi) {
        const int r0 = m0 + wm + mi * 16 + g;
#pragma unroll
        for (int ni = 0; ni < 4; ++ni) {
            const int col = n0 + wn + ni * 8 + tg;
            const float b0v = J.bias[col], b1v = J.bias[col + 1];
            float v00 = acc[mi][ni][0] + b0v, v01 = acc[mi][ni][1] + b1v;
            float v10 = acc[mi][ni][2] + b0v, v11 = acc[mi][ni][3] + b1v;
            const size_t o0 = (size_t)r0 * 512 + col;
            const size_t o1 = (size_t)(r0 + 8) * 512 + col;
            if (J.mode == 0) {
                float2 lo = {v00, v01};
                float2 hi = {v10, v11};
                *(float2*)&J.C[o0] = lo;
                *(float2*)&J.C[o1] = hi;
            } else {
                split2w(v00, v01, J.Ch + o0, J.Cl + o0);
                split2w(v10, v11, J.Ch + o1, J.Cl + o1);
            }
        }
    }
}

// ---------------------------------------------------------------------------
// scores (HMMA): per (b,h): At = 0.125 * (qh+ql)(kh+kl)^T
// ---------------------------------------------------------------------------
__global__ __launch_bounds__(NT)
void scores_hmma_kernel(const __nv_bfloat16* __restrict__ qh,
                        const __nv_bfloat16* __restrict__ ql,
                        const __nv_bfloat16* __restrict__ kh,
                        const __nv_bfloat16* __restrict__ kl,
                        float* __restrict__ At)
{
    extern __shared__ __align__(16) __nv_bfloat16 smem[];
    const uint32_t smemU = (uint32_t)__cvta_generic_to_shared(smem);
    const int bh = blockIdx.z, b = bh >> 3, h = bh & 7;
    const int m0 = blockIdx.y * 128, n0 = blockIdx.x * 128;
    const int tid = threadIdx.x, lane = tid & 31, wid = tid >> 5;
    const int wm = (wid & 3) * 32, wn = (wid >> 2) * 64;

    const int row = tid >> 1, off = (tid & 1) * 32;
    const size_t qsrc = (size_t)(b * 1024 + m0 + row) * 512 + h * 64 + off;
    const size_t ksrc = (size_t)(b * 1024 + n0 + row) * 512 + h * 64 + off;
    const uint32_t dst = (row * ASTRIDE + off) * 2;
#pragma unroll
    for (int i = 0; i < 4; ++i) {
        cpa16(smemU + 0 * SC_TILE + dst + i * 16, qh + qsrc + i * 8);
        cpa16(smemU + 1 * SC_TILE + dst + i * 16, ql + qsrc + i * 8);
        cpa16(smemU + 2 * SC_TILE + dst + i * 16, kh + ksrc + i * 8);
        cpa16(smemU + 3 * SC_TILE + dst + i * 16, kl + ksrc + i * 8);
    }
    CP_COMMIT();
    CP_WAIT(0);
    __syncthreads();

    float acc[2][8][4] = {};
    const uint32_t aFrag =
        ((wm + (lane & 15)) * ASTRIDE + ((lane >> 4) & 1) * 8) * 2;
    const uint32_t bFrag =
        ((wn + (lane & 7) + ((lane >> 4) & 1) * 8) * ASTRIDE +
         ((lane >> 3) & 1) * 8) * 2;

    const uint32_t aoffs[3] = {0u, SC_TILE, 0u};
    const uint32_t boffs[3] = {2u * SC_TILE, 2u * SC_TILE, 3u * SC_TILE};
#pragma unroll
    for (int pass = 0; pass < 3; ++pass) {
        const uint32_t aA = smemU + aoffs[pass] + aFrag;
        const uint32_t bA = smemU + boffs[pass] + bFrag;
#pragma unroll
        for (int k16 = 0; k16 < 4; ++k16) {
            const uint32_t ko = k16 * 32;
            uint32_t a0[4], a1[4], bf[4][4];
            LDSM4(a0, aA + ko);
            LDSM4(a1, aA + 16 * ASTRIDE * 2 + ko);
#pragma unroll
            for (int p = 0; p < 4; ++p)
                LDSM4(bf[p], bA + p * 16 * ASTRIDE * 2 + ko);
#pragma unroll
            for (int p = 0; p < 4; ++p) {
                mma16816(acc[0][2 * p],     a0, bf[p]);
                mma16816(acc[0][2 * p + 1], a0, bf[p] + 2);
                mma16816(acc[1][2 * p],     a1, bf[p]);
                mma16816(acc[1][2 * p + 1], a1, bf[p] + 2);
            }
        }
    }

    float* Cp = At + ((size_t)bh << 20);
    const int g = lane >> 2, tg = (lane & 3) * 2;
#pragma unroll
    for (int mi = 0; mi < 2; ++mi) {
        const int r0 = m0 + wm + mi * 16 + g;
#pragma unroll
        for (int ni = 0; ni < 8; ++ni) {
            const int col = n0 + wn + ni * 8 + tg;
            float2 lo = {acc[mi][ni][0] * 0.125f, acc[mi][ni][1] * 0.125f};
            float2 hi = {acc[mi][ni][2] * 0.125f, acc[mi][ni][3] * 0.125f};
            *(float2*)&Cp[(size_t)r0 * 1024 + col] = lo;
            *(float2*)&Cp[(size_t)(r0 + 8) * 1024 + col] = hi;
        }
    }
}

// ---------------------------------------------------------------------------
// fused softmax / z / masks / stats; emits (t-1) bf16 hi/lo planes
// ---------------------------------------------------------------------------
__device__ __forceinline__ float warpMaxF(float v) {
#pragma unroll
    for (int o = 16; o; o >>= 1) v = fmaxf(v, __shfl_xor_sync(0xffffffffu, v, o));
    return v;
}
__device__ __forceinline__ float warpSumF(float v) {
#pragma unroll
    for (int o = 16; o; o >>= 1) v += __shfl_xor_sync(0xffffffffu, v, o);
    return v;
}

__global__ __launch_bounds__(NT)
void fused_sm_kernel(const float* __restrict__ At,
                     const float* __restrict__ cw,
                     const float* __restrict__ cbp,
                     unsigned char* __restrict__ maskbuf,
                     float* __restrict__ stats,
                     __nv_bfloat16* __restrict__ tdh,
                     __nv_bfloat16* __restrict__ tdl)
{
    const int bq = blockIdx.x;
    const int b  = bq >> 10;
    const int q  = bq & 1023;
    const int tid  = threadIdx.x;
    const int lane = tid & 31, wid = tid >> 5;

    __shared__ float red[16][8];
    __shared__ float fin[16];

    const float cb = cbp[0];
    const size_t rowbase = ((size_t)q << 10) + (size_t)tid * 4;

    float a[8][4];
    float lm[8];
#pragma unroll
    for (int h = 0; h < 8; ++h) {
        float4 v = *(const float4*)(At + (size_t)(b * 8 + h) * 1048576 + rowbase);
        a[h][0] = v.x; a[h][1] = v.y; a[h][2] = v.z; a[h][3] = v.w;
        lm[h] = fmaxf(fmaxf(v.x, v.y), fmaxf(v.z, v.w));
    }
#pragma unroll
    for (int h = 0; h < 8; ++h) {
        float w = warpMaxF(lm[h]);
        if (lane == 0) red[h][wid] = w;
    }
    __syncthreads();
    if (tid < 8) {
        float m = red[tid][0];
#pragma unroll
        for (int i = 1; i < 8; ++i) m = fmaxf(m, red[tid][i]);
        fin[tid] = m;
    }
    __syncthreads();
    float ls[8];
#pragma unroll
    for (int h = 0; h < 8; ++h) {
        float m = fin[h];
        float s = 0.f;
#pragma unroll
        for (int j = 0; j < 4; ++j) {
            a[h][j] = __expf(a[h][j] - m);
            s += a[h][j];
        }
        ls[h] = s;
    }
    __syncthreads();
#pragma unroll
    for (int h = 0; h < 8; ++h) {
        float w = warpSumF(ls[h]);
        if (lane == 0) red[h][wid] = w;
    }
    __syncthreads();
    if (tid < 8) {
        float s = red[tid][0];
#pragma unroll
        for (int i = 1; i < 8; ++i) s += red[tid][i];
        fin[tid] = 1.0f / s;
    }
    __syncthreads();

    float zacc[4] = {cb, cb, cb, cb};
#pragma unroll
    for (int h = 0; h < 8; ++h) {
        float inv = fin[h];
        float w   = cw[h];
#pragma unroll
        for (int j = 0; j < 4; ++j) {
            a[h][j] *= inv;
            zacc[j] = fmaf(a[h][j], w, zacc[j]);
        }
    }
    unsigned mby[4];
#pragma unroll
    for (int j = 0; j < 4; ++j) {
        unsigned mf = (zacc[j] <= 0.f) ? 1u : 0u;
        unsigned mr = (zacc[j] >= 0.f) ? 2u : 0u;
        mby[j] = mf | mr;
    }

    float lsf[8], lsr[8];
#pragma unroll
    for (int h = 0; h < 8; ++h) {
        float sf = 0.f, sr = 0.f;
#pragma unroll
        for (int j = 0; j < 4; ++j) {
            float t = __expf(a[h][j]);
            a[h][j] = t;
            sf += (mby[j] & 1u) ? t : 1.0f;
            sr += (mby[j] & 2u) ? t : 1.0f;
        }
        lsf[h] = sf; lsr[h] = sr;
    }
    __syncthreads();
#pragma unroll
    for (int h = 0; h < 8; ++h) {
        float w = warpSumF(lsf[h]);
        if (lane == 0) red[h][wid] = w;
        w = warpSumF(lsr[h]);
        if (lane == 0) red[8 + h][wid] = w;
    }
    __syncthreads();
    if (tid < 16) {
        float s = red[tid][0];
#pragma unroll
        for (int i = 1; i < 8; ++i) s += red[tid][i];
        float inv = 1.0f / s;
        int h = tid & 7;
        int row = (b * 8 + h) * 1024 + q;
        if (tid < 8) stats[row] = inv;
        else         stats[32768 + row] = inv;
    }

    // write (t-1) hi/lo splits + mask bytes
#pragma unroll
    for (int h = 0; h < 8; ++h) {
        size_t o = (size_t)(b * 8 + h) * 1048576 + rowbase;
        split2w(a[h][0] - 1.0f, a[h][1] - 1.0f, tdh + o, tdl + o);
        split2w(a[h][2] - 1.0f, a[h][3] - 1.0f, tdh + o + 2, tdl + o + 2);
    }
    uchar4 m4 = {(unsigned char)mby[0], (unsigned char)mby[1],
                 (unsigned char)mby[2], (unsigned char)mby[3]};
    *(uchar4*)(maskbuf + (size_t)bq * 1024 + tid * 4) = m4;
}

// ---------------------------------------------------------------------------
// colsum[bh][d] = sum_k (vh+vl)[b,k,h*64+d]
// ---------------------------------------------------------------------------
__global__ __launch_bounds__(NT)
void colsum_kernel(const __nv_bfloat16* __restrict__ vh,
                   const __nv_bfloat16* __restrict__ vl,
                   float* __restrict__ cs)
{
    const int bh = blockIdx.x, b = bh >> 3, h = bh & 7;
    const int tid = threadIdx.x;
    const int d = tid & 63, part = tid >> 6;   // 4 parts x 256 k
    __shared__ float red[4][64];
    const __nv_bfloat16* p1 = vh + ((size_t)(b * 1024 + part * 256)) * 512 + h * 64 + d;
    const __nv_bfloat16* p2 = vl + ((size_t)(b * 1024 + part * 256)) * 512 + h * 64 + d;
    float s = 0.f;
    for (int k = 0; k < 256; ++k)
        s += __bfloat162float(p1[(size_t)k * 512]) + __bfloat162float(p2[(size_t)k * 512]);
    red[part][d] = s;
    __syncthreads();
    if (tid < 64)
        cs[bh * 64 + tid] = red[0][tid] + red[1][tid] + red[2][tid] + red[3][tid];
}

// ---------------------------------------------------------------------------
// av (HMMA): per (b,h), q-tile 64:
//   S_f[q][d] = sum_k (m_f ? (t-1) : 0)[q][k] * v[k][d]     (3 split passes)
//   T_f = (S_f + colsum)*rsf  -> bf16 hi/lo;   same for r branch.
// warps 0-3: f, warps 4-7: r.
// ---------------------------------------------------------------------------
__global__ __launch_bounds__(NT)
void av_hmma_kernel(const __nv_bfloat16* __restrict__ tdh,
                    const __nv_bfloat16* __restrict__ tdl,
                    const unsigned char* __restrict__ maskb,
                    const float* __restrict__ stats,
                    const float* __restrict__ colsum,
                    const __nv_bfloat16* __restrict__ vh,
                    const __nv_bfloat16* __restrict__ vl,
                    __nv_bfloat16* __restrict__ Tfh, __nv_bfloat16* __restrict__ Tfl,
                    __nv_bfloat16* __restrict__ Trh, __nv_bfloat16* __restrict__ Trl)
{
    extern __shared__ __align__(16) __nv_bfloat16 smem[];
    const uint32_t smemU = (uint32_t)__cvta_generic_to_shared(smem);
    const int bh = blockIdx.y, b = bh >> 3, h = bh & 7;
    const int q0 = blockIdx.x * 64;
    const int tid = threadIdx.x, lane = tid & 31, wid = tid >> 5;
    const int branch = wid >> 2;          // 0=f, 1=r
    const int wq = (wid & 3) * 16;

    const int row = tid >> 2, seg = (tid & 3) * 16;

    const __nv_bfloat16* thp = tdh + (size_t)bh * 1048576 + (size_t)(q0 + row) * 1024 + seg;
    const __nv_bfloat16* tlp = tdl + (size_t)bh * 1048576 + (size_t)(q0 + row) * 1024 + seg;
    const unsigned char* mp  = maskb + ((size_t)(b * 1024 + q0 + row)) * 1024 + seg;
    const __nv_bfloat16* vhp = vh + ((size_t)(b * 1024 + row)) * 512 + h * 64 + seg;
    const __nv_bfloat16* vlp = vl + ((size_t)(b * 1024 + row)) * 512 + h * 64 + seg;

    uint4 thR[2], tlR[2], mkR;
    auto loadA = [&](int c) {
        const int k0 = c * 64;
        thR[0] = *(const uint4*)(thp + k0);
        thR[1] = *(const uint4*)(thp + k0 + 8);
        tlR[0] = *(const uint4*)(tlp + k0);
        tlR[1] = *(const uint4*)(tlp + k0 + 8);
        mkR    = *(const uint4*)(mp + k0);
    };
    auto issueV = [&](int c, int buf) {
        const size_t ko = (size_t)c * 64 * 512;
        const uint32_t base = smemU + buf * (AV_STAGE * 2) + (row * ASTRIDE + seg) * 2;
        cpa16(base + AV_VH * 2,      vhp + ko);
        cpa16(base + AV_VH * 2 + 16, vhp + ko + 8);
        cpa16(base + AV_VL * 2,      vlp + ko);
        cpa16(base + AV_VL * 2 + 16, vlp + ko + 8);
        CP_COMMIT();
    };
    auto selstore = [&](int buf) {
        const uint32_t* thw = (const uint32_t*)thR;
        const uint32_t* tlw = (const uint32_t*)tlR;
        uint32_t mkw[4] = {mkR.x, mkR.y, mkR.z, mkR.w};
        uint32_t afh[8], afl[8], arh[8], arl[8];
#pragma unroll
        for (int i = 0; i < 8; ++i) {
            uint32_t mw = mkw[i >> 1];
            uint32_t sh = (i & 1) * 16;
            uint32_t m0 = (mw >> sh) & 0xFFu;
            uint32_t m1 = (mw >> (sh + 8)) & 0xFFu;
            uint32_t sF = ((m0 & 1u) ? 0x0000FFFFu : 0u) | ((m1 & 1u) ? 0xFFFF0000u : 0u);
            uint32_t sR = ((m0 & 2u) ? 0x0000FFFFu : 0u) | ((m1 & 2u) ? 0xFFFF0000u : 0u);
            afh[i] = thw[i] & sF;  arh[i] = thw[i] & sR;
            afl[i] = tlw[i] & sF;  arl[i] = tlw[i] & sR;
        }
        const uint32_t base = smemU + buf * (AV_STAGE * 2) + (row * ASTRIDE + seg) * 2;
        STS128(base + AV_AFH * 2,      afh[0], afh[1], afh[2], afh[3]);
        STS128(base + AV_AFH * 2 + 16, afh[4], afh[5], afh[6], afh[7]);
        STS128(base + AV_AFL * 2,      afl[0], afl[1], afl[2], afl[3]);
        STS128(base + AV_AFL * 2 + 16, afl[4], afl[5], afl[6], afl[7]);
        STS128(base + AV_ARH * 2,      arh[0], arh[1], arh[2], arh[3]);
        STS128(base + AV_ARH * 2 + 16, arh[4], arh[5], arh[6], arh[7]);
        STS128(base + AV_ARL * 2,      arl[0], arl[1], arl[2], arl[3]);
        STS128(base + AV_ARL * 2 + 16, arl[4], arl[5], arl[6], arl[7]);
    };

    float acc[8][4] = {};
    const uint32_t aOffH = (branch ? AV_ARH : AV_AFH) * 2 +
        ((wq + (lane & 15)) * ASTRIDE + ((lane >> 4) & 1) * 8) * 2;
    const uint32_t aOffL = (branch ? AV_ARL : AV_AFL) * 2 +
        ((wq + (lane & 15)) * ASTRIDE + ((lane >> 4) & 1) * 8) * 2;
    const uint32_t vLaneOff = ((lane & 15) * ASTRIDE + ((lane >> 4) & 1) * 8) * 2;

    auto compute = [&](int buf) {
        const uint32_t sb = smemU + buf * (AV_STAGE * 2);
#pragma unroll
        for (int k16 = 0; k16 < 4; ++k16) {
            uint32_t ah[4], al[4], fvh[16], fvl[16];
            LDSM4(ah, sb + aOffH + k16 * 32);
            LDSM4(al, sb + aOffL + k16 * 32);
            const uint32_t vkb = sb + vLaneOff + k16 * 16 * ASTRIDE * 2;
#pragma unroll
            for (int g = 0; g < 4; ++g) {
                LDSM4T(fvh + 4 * g, vkb + AV_VH * 2 + g * 32);
                LDSM4T(fvl + 4 * g, vkb + AV_VL * 2 + g * 32);
            }
#pragma unroll
            for (int n = 0; n < 8; ++n) {
                uint32_t* bh2 = fvh + 4 * (n >> 1) + 2 * (n & 1);
                uint32_t* bl2 = fvl + 4 * (n >> 1) + 2 * (n & 1);
                mma16816(acc[n], ah, bh2);
                mma16816(acc[n], ah, bl2);
                mma16816(acc[n], al, bh2);
            }
        }
    };

    // prologue
    loadA(0);
    issueV(0, 0);
    selstore(0);
    CP_WAIT(0);
    __syncthreads();

    for (int c = 0; c < 16; ++c) {
        const int cur = c & 1;
        const bool more = (c + 1) < 16;
        if (more) { issueV(c + 1, cur ^ 1); loadA(c + 1); }
        compute(cur);
        __syncthreads();
        if (more) {
            selstore(cur ^ 1);
            CP_WAIT(0);
            __syncthreads();
        }
    }

    // epilogue
    const int g = lane >> 2, tg = (lane & 3) * 2;
    const int q1 = q0 + wq + g, q2 = q1 + 8;
    const int srow = (branch ? 32768 : 0) + bh * 1024;
    const float rs1 = stats[srow + q1];
    const float rs2 = stats[srow + q2];
    __nv_bfloat16* outH = branch ? Trh : Tfh;
    __nv_bfloat16* outL = branch ? Trl : Tfl;
#pragma unroll
    for (int n = 0; n < 8; ++n) {
        const int d = n * 8 + tg;
        const float cs0 = colsum[bh * 64 + d];
        const float cs1 = colsum[bh * 64 + d + 1];
        const size_t o1 = (size_t)(b * 1024 + q1) * 512 + h * 64 + d;
        const size_t o2 = (size_t)(b * 1024 + q2) * 512 + h * 64 + d;
        split2w((acc[n][0] + cs0) * rs1, (acc[n][1] + cs1) * rs1, outH + o1, outL + o1);
        split2w((acc[n][2] + cs0) * rs2, (acc[n][3] + cs1) * rs2, outH + o2, outL + o2);
    }
}

// ---------------------------------------------------------------------------
__global__ __launch_bounds__(NT)
void combine_kernel(const float* __restrict__ Ff, const float* __restrict__ Gf,
                    const float* __restrict__ Fr, const float* __restrict__ Gr,
                    float* __restrict__ out)
{
    const size_t i4 = (size_t)blockIdx.x * NT + threadIdx.x;
    float4 ff = ((const float4*)Ff)[i4];
    float4 gf = ((const float4*)Gf)[i4];
    float4 fr = ((const float4*)Fr)[i4];
    float4 gr = ((const float4*)Gr)[i4];

    float ffv[4] = {ff.x, ff.y, ff.z, ff.w};
    float gfv[4] = {gf.x, gf.y, gf.z, gf.w};
    float frv[4] = {fr.x, fr.y, fr.z, fr.w};
    float grv[4] = {gr.x, gr.y, gr.z, gr.w};
    float ov[4];
#pragma unroll
    for (int j = 0; j < 4; ++j) {
        float sgf = 1.0f / (1.0f + __expf(-gfv[j]));
        float sgr = 1.0f / (1.0f + __expf(-grv[j]));
        float w   = 1.0f / (1.0f + __expf(sgr - sgf));
        ov[j] = ffv[j] * w + frv[j] * (1.0f - w);
    }
    float4 o = {ov[0], ov[1], ov[2], ov[3]};
    ((float4*)out)[i4] = o;
}

// ---------------------------------------------------------------------------
extern "C" void kernel_launch(void* const* d_in, const int* in_sizes, int n_in,
                              void* d_out, int out_size)
{
    const float* x   = (const float*)d_in[0];
    const float* Wq  = (const float*)d_in[1];
    const float* bq  = (const float*)d_in[2];
    const float* Wk  = (const float*)d_in[3];
    const float* bk  = (const float*)d_in[4];
    const float* Wv  = (const float*)d_in[5];
    const float* bv  = (const float*)d_in[6];
    const float* cw  = (const float*)d_in[7];
    const float* cb  = (const float*)d_in[8];
    const float* Wfh = (const float*)d_in[9];
    const float* bfh = (const float*)d_in[10];
    const float* Wfg = (const float*)d_in[11];
    const float* bfg = (const float*)d_in[12];
    const float* Wrh = (const float*)d_in[13];
    const float* brh = (const float*)d_in[14];
    const float* Wrg = (const float*)d_in[15];
    const float* brg = (const float*)d_in[16];
    float* out = (float*)d_out;

    float* s = nullptr;
    cudaGetSymbolAddress((void**)&s, g_scratch);
    __nv_bfloat16* bb = nullptr;
    cudaGetSymbolAddress((void**)&bb, g_bfbuf);

    float* Ff    = s + OFF_FF;
    float* Gf    = s + OFF_GF;
    float* Fr    = s + OFF_FR;
    float* Gr    = s + OFF_GR;
    unsigned char* maskb = (unsigned char*)(s + OFF_MB);
    float* stats = s + OFF_ST;
    float* csum  = s + OFF_CS;
    float* At    = s + OFF_AT;

    __nv_bfloat16* xh  = bb + BX_H;
    __nv_bfloat16* xl  = bb + BX_L;
    __nv_bfloat16* tfh = bb + BTF_H;
    __nv_bfloat16* tfl = bb + BTF_L;
    __nv_bfloat16* trh = bb + BTR_H;
    __nv_bfloat16* trl = bb + BTR_L;
    __nv_bfloat16* wb  = bb + BW;
    __nv_bfloat16* qhb = bb + BQ_H;
    __nv_bfloat16* qlb = bb + BQ_L;
    __nv_bfloat16* khb = bb + BK_H;
    __nv_bfloat16* klb = bb + BK_L;
    __nv_bfloat16* vhb = bb + BV_H;
    __nv_bfloat16* vlb = bb + BV_L;
    __nv_bfloat16* tdh = bb + BT_H;
    __nv_bfloat16* tdl = bb + BT_L;

    cudaFuncSetAttribute(hmma_gemm_kernel,
                         cudaFuncAttributeMaxDynamicSharedMemorySize, HM_SMEM);
    cudaFuncSetAttribute(scores_hmma_kernel,
                         cudaFuncAttributeMaxDynamicSharedMemorySize, SC_SMEM);
    cudaFuncSetAttribute(av_hmma_kernel,
                         cudaFuncAttributeMaxDynamicSharedMemorySize, AV_SMEM);

    WPack wp;
    wp.w[0] = Wq;  wp.w[1] = Wk;  wp.w[2] = Wv;
    wp.w[3] = Wfh; wp.w[4] = Wfg; wp.w[5] = Wrh; wp.w[6] = Wrg;
    splitw_kernel<<<dim3(16, 16, 7), NT>>>(wp, wb);
    splitx_kernel<<<2048, NT>>>(x, xh, xl);

    // qkv (merged launch)
    GJobs qkv = {};
    qkv.j[0] = {xh, xl, wb + 0 * 524288, wb + 0 * 524288 + 262144, bq, nullptr, qhb, qlb, 1};
    qkv.j[1] = {xh, xl, wb + 1 * 524288, wb + 1 * 524288 + 262144, bk, nullptr, khb, klb, 1};
    qkv.j[2] = {xh, xl, wb + 2 * 524288, wb + 2 * 524288 + 262144, bv, nullptr, vhb, vlb, 1};
    hmma_gemm_kernel<<<dim3(8, 32, 3), NT, HM_SMEM>>>(qkv);

    scores_hmma_kernel<<<dim3(8, 8, 32), NT, SC_SMEM>>>(qhb, qlb, khb, klb, At);
    fused_sm_kernel<<<4096, NT>>>(At, cw, cb, maskb, stats, tdh, tdl);
    colsum_kernel<<<32, NT>>>(vhb, vlb, csum);
    av_hmma_kernel<<<dim3(16, 32), NT, AV_SMEM>>>(tdh, tdl, maskb, stats, csum,
                                                  vhb, vlb, tfh, tfl, trh, trl);

    // final 4 gemms (merged launch)
    GJobs fin = {};
    fin.j[0] = {tfh, tfl, wb + 3 * 524288, wb + 3 * 524288 + 262144, bfh, Ff, nullptr, nullptr, 0};
    fin.j[1] = {tfh, tfl, wb + 4 * 524288, wb + 4 * 524288 + 262144, bfg, Gf, nullptr, nullptr, 0};
    fin.j[2] = {trh, trl, wb + 5 * 524288, wb + 5 * 524288 + 262144, brh, Fr, nullptr, nullptr, 0};
    fin.j[3] = {trh, trl, wb + 6 * 524288, wb + 6 * 524288 + 262144, brg, Gr, nullptr, nullptr, 0};
    hmma_gemm_kernel<<<dim3(8, 32, 4), NT, HM_SMEM>>>(fin);

    combine_kernel<<<2048, NT>>>(Ff, Gf, Fr, Gr, out);
}